// round 12
// baseline (speedup 1.0000x reference)
#include <cuda_runtime.h>
#include <cuda_fp16.h>
#include <math.h>
#include <stdint.h>

#define NNODES 50000
#define NEDGES 600000
#define DM 128
#define HH 8
#define DH 16
#define DFFH 512
#define LL 3
#define MTILES ((NNODES + 127) / 128)   // 391
#define FTILES ((NNODES + 63) / 64)     // 782

// ---------------- scratch (static device memory; no allocs allowed) --------
__device__ __half g_z [(size_t)NNODES * DM];     // fp16 projected features
__device__ __half g_xr[(size_t)NNODES * DM];     // fp16 layer input
__device__ float  g_el[(size_t)NNODES * HH];
__device__ float  g_er[(size_t)NNODES * HH];
__device__ float  g_h [(size_t)NNODES * DM];
__device__ __half g_hn[(size_t)NNODES * DM];     // fp16
__device__ __half g_bt[(size_t)3 * (DM * DM + DM * DFFH + DFFH * DM)]; // all W^T fp16
__device__ int    g_cnt[NNODES + 1];             // counts -> rowptr
__device__ int    g_wo [NNODES];                 // scatter write offsets
__device__ int    g_adj[NEDGES];                 // src ids grouped by dst

#define OFF_W(l)  ((size_t)(l) * DM * DM)
#define OFF_W1(l) ((size_t)3 * DM * DM + (size_t)(l) * DM * DFFH)
#define OFF_W2(l) ((size_t)3 * DM * DM + (size_t)3 * DM * DFFH + (size_t)(l) * DFFH * DM)

// ---------------- helpers ------------------------------------------------
__device__ __forceinline__ uint32_t smem_u32(const void* p) {
    uint32_t a;
    asm("{ .reg .u64 t; cvta.to.shared.u64 t, %1; cvt.u32.u64 %0, t; }" : "=r"(a) : "l"(p));
    return a;
}
__device__ __forceinline__ void cp_async16(uint32_t saddr, const void* gaddr, uint32_t sz) {
    asm volatile("cp.async.cg.shared.global [%0], [%1], 16, %2;"
                 :: "r"(saddr), "l"(gaddr), "r"(sz) : "memory");
}
// fp16 mma: D(f32) += A(f16, m16k16) * B(f16, k16n8)
__device__ __forceinline__ void mma_f16(float* c, const uint32_t* a, const uint32_t* b) {
    asm volatile("mma.sync.aligned.m16n8k16.row.col.f32.f16.f16.f32 "
                 "{%0,%1,%2,%3}, {%4,%5,%6,%7}, {%8,%9}, {%0,%1,%2,%3};"
                 : "+f"(c[0]), "+f"(c[1]), "+f"(c[2]), "+f"(c[3])
                 : "r"(a[0]), "r"(a[1]), "r"(a[2]), "r"(a[3]),
                   "r"(b[0]), "r"(b[1]));
}
__device__ __forceinline__ void ldsm4(uint32_t addr, uint32_t& r0, uint32_t& r1,
                                      uint32_t& r2, uint32_t& r3) {
    asm volatile("ldmatrix.sync.aligned.m8n8.x4.shared.b16 {%0,%1,%2,%3}, [%4];"
                 : "=r"(r0), "=r"(r1), "=r"(r2), "=r"(r3) : "r"(addr));
}

#define HP 24                              // halves per staged row (16 + 8 pad)
#define HSTAGEB (128 * HP * 2)             // 6144 bytes per matrix per k16 stage
#define NSTAGE 3
#define G0SMEM (2 * NSTAGE * HSTAGEB)      // 36864 bytes

// ---------------- fp16 mma GEMM: z-projection + fused el/er ------------------
__global__ void __launch_bounds__(256, 2) gemm_z(
    const __half* __restrict__ A, const __half* __restrict__ Bt,
    __half* __restrict__ C,
    const float* __restrict__ attn_l, const float* __restrict__ attn_r)
{
    extern __shared__ char smem_raw[];
    __shared__ float sAL[DM], sAR[DM];

    const int tid  = threadIdx.x;
    const int lane = tid & 31;
    const int wid  = tid >> 5;
    const int warpm = wid & 3;          // 4 warps along M (32 rows)
    const int warpn = wid >> 2;         // 2 warps along N (64 cols)
    const int rowBase = blockIdx.y * 128;

    if (tid < DM) { sAL[tid] = attn_l[tid]; sAR[tid] = attn_r[tid]; }
    __syncthreads();

    const uint32_t aS = smem_u32(smem_raw);
    const uint32_t bS = aS + NSTAGE * HSTAGEB;

    const uint32_t aBase = aS +
        (uint32_t)(((warpm * 32) + (((lane >> 3) & 1) * 8) + (lane & 7)) * HP
                   + (lane >> 4) * 8) * 2;
    const uint32_t bBase = bS +
        (uint32_t)(((warpn * 64) + (((lane >> 4) & 1) * 8) + (lane & 7)) * HP
                   + ((lane >> 3) & 1) * 8) * 2;

    auto load_stage = [&](int buf, int k0) {
        int row = tid >> 1;
        int kc  = (tid & 1) * 8;
        int gr = rowBase + row;
        cp_async16(aS + (uint32_t)(row * HP + kc) * 2 + buf * HSTAGEB,
                   A + (size_t)(gr < NNODES ? gr : 0) * DM + k0 + kc,
                   (gr < NNODES) ? 16u : 0u);
        cp_async16(bS + (uint32_t)(row * HP + kc) * 2 + buf * HSTAGEB,
                   Bt + (size_t)row * DM + k0 + kc, 16u);
        asm volatile("cp.async.commit_group;" ::: "memory");
    };

    float acc[2][8][4];
    #pragma unroll
    for (int ms = 0; ms < 2; ms++)
        #pragma unroll
        for (int ns = 0; ns < 8; ns++)
            #pragma unroll
            for (int q = 0; q < 4; q++) acc[ms][ns][q] = 0.0f;

    load_stage(0, 0);
    load_stage(1, 16);

    #pragma unroll
    for (int kt = 0; kt < 8; ++kt) {
        if (kt + 1 < 8) asm volatile("cp.async.wait_group 1;" ::: "memory");
        else            asm volatile("cp.async.wait_group 0;" ::: "memory");
        __syncthreads();
        if (kt + 2 < 8) load_stage((kt + 2) % NSTAGE, (kt + 2) * 16);

        const uint32_t kOff = (uint32_t)((kt % NSTAGE) * HSTAGEB);
        uint32_t a[2][4], b[8][2];
        ldsm4(aBase + kOff, a[0][0], a[0][1], a[0][2], a[0][3]);
        ldsm4(aBase + kOff + 16 * HP * 2, a[1][0], a[1][1], a[1][2], a[1][3]);
        #pragma unroll
        for (int p = 0; p < 4; p++)
            ldsm4(bBase + kOff + (uint32_t)(p * 16 * HP * 2),
                  b[2 * p][0], b[2 * p][1], b[2 * p + 1][0], b[2 * p + 1][1]);
        #pragma unroll
        for (int ms = 0; ms < 2; ms++)
            #pragma unroll
            for (int ns = 0; ns < 8; ns++)
                mma_f16(acc[ms][ns], a[ms], b[ns]);
    }

    // epilogue: store z (fp16) + fused el/er (from fp32 acc)
    #pragma unroll
    for (int ms = 0; ms < 2; ms++) {
        #pragma unroll
        for (int half = 0; half < 2; half++) {
            int r = rowBase + warpm * 32 + ms * 16 + half * 8 + (lane >> 2);
            const bool valid = (r < NNODES);
            float psl[4], psr[4];
            #pragma unroll
            for (int q = 0; q < 4; q++) { psl[q] = 0.f; psr[q] = 0.f; }
            #pragma unroll
            for (int ns = 0; ns < 8; ns++) {
                int cl = warpn * 64 + ns * 8 + (lane & 3) * 2;
                float v0 = acc[ms][ns][half * 2 + 0];
                float v1 = acc[ms][ns][half * 2 + 1];
                if (valid)
                    *(__half2*)&C[(size_t)r * DM + cl] = __floats2half2_rn(v0, v1);
                int hh = ns >> 1;
                psl[hh] += v0 * sAL[cl] + v1 * sAL[cl + 1];
                psr[hh] += v0 * sAR[cl] + v1 * sAR[cl + 1];
            }
            #pragma unroll
            for (int d = 1; d <= 2; d <<= 1) {
                #pragma unroll
                for (int q = 0; q < 4; q++) {
                    psl[q] += __shfl_xor_sync(0xFFFFFFFFu, psl[q], d);
                    psr[q] += __shfl_xor_sync(0xFFFFFFFFu, psr[q], d);
                }
            }
            if ((lane & 3) == 0 && valid) {
                #pragma unroll
                for (int q = 0; q < 4; q++) {
                    int hidx = r * HH + warpn * 4 + q;
                    g_el[hidx] = psl[q];
                    g_er[hidx] = psr[q];
                }
            }
        }
    }
}

// ---------------- fused FeedForward (fp16): 64-row blocks --------------------
#define FPH 136
#define FF_A (64 * FPH * 2)
#define FF_SMEM (2 * FF_A + NSTAGE * HSTAGEB)

__global__ void __launch_bounds__(256, 2) ff_fused(
    const __half* __restrict__ hn, const __half* __restrict__ Bt1,
    const __half* __restrict__ Bt2,
    const float* __restrict__ b1, const float* __restrict__ slope,
    const float* __restrict__ b2, const float* __restrict__ hres,
    float* __restrict__ Cout, __half* __restrict__ xr)
{
    extern __shared__ char smem_raw[];
    const int tid  = threadIdx.x;
    const int lane = tid & 31;
    const int wid  = tid >> 5;
    const int warpm = wid & 1;
    const int warpn = wid >> 1;
    const int rowBase = blockIdx.x * 64;

    const uint32_t hnS = smem_u32(smem_raw);
    const uint32_t tS  = hnS + FF_A;
    const uint32_t bS  = tS + FF_A;
    __half* tHalf = (__half*)(smem_raw + FF_A);

    const uint32_t aLane =
        (uint32_t)(((warpm * 32) + (((lane >> 3) & 1) * 8) + (lane & 7)) * FPH
                   + (lane >> 4) * 8) * 2;
    const uint32_t bLane =
        (uint32_t)(((warpn * 32) + (((lane >> 4) & 1) * 8) + (lane & 7)) * HP
                   + ((lane >> 3) & 1) * 8) * 2;

    #pragma unroll
    for (int i = 0; i < 4; i++) {
        int chunk = tid + i * 256;
        int m = chunk >> 4;
        int q = (chunk & 15) * 8;
        int gr = rowBase + m;
        cp_async16(hnS + (uint32_t)(m * FPH + q) * 2,
                   hn + (size_t)(gr < NNODES ? gr : 0) * DM + q,
                   (gr < NNODES) ? 16u : 0u);
    }
    asm volatile("cp.async.commit_group;" ::: "memory");

    float accO[2][4][4];
    #pragma unroll
    for (int ms = 0; ms < 2; ms++)
        #pragma unroll
        for (int ns = 0; ns < 4; ns++)
            #pragma unroll
            for (int q = 0; q < 4; q++) accO[ms][ns][q] = 0.0f;

    const float slp = __ldg(slope);

    auto run_gemm = [&](uint32_t aSm, const __half* Bbase, int bstr,
                        float (*acc)[4][4]) {
        auto loadB = [&](int buf, int kt) {
            int row = tid >> 1;
            int kq  = (tid & 1) * 8;
            cp_async16(bS + (uint32_t)(row * HP + kq) * 2 + buf * HSTAGEB,
                       Bbase + (size_t)row * bstr + kt * 16 + kq, 16u);
            asm volatile("cp.async.commit_group;" ::: "memory");
        };
        __syncthreads();
        loadB(0, 0);
        loadB(1, 1);
        #pragma unroll
        for (int kt = 0; kt < 8; kt++) {
            if (kt + 1 < 8) asm volatile("cp.async.wait_group 1;" ::: "memory");
            else            asm volatile("cp.async.wait_group 0;" ::: "memory");
            __syncthreads();
            if (kt + 2 < 8) loadB((kt + 2) % NSTAGE, kt + 2);

            uint32_t a[2][4], b[4][2];
            const uint32_t ak = aSm + aLane + (uint32_t)(kt * 16) * 2;
            ldsm4(ak, a[0][0], a[0][1], a[0][2], a[0][3]);
            ldsm4(ak + 16 * FPH * 2, a[1][0], a[1][1], a[1][2], a[1][3]);
            const uint32_t bk = bS + bLane + (uint32_t)((kt % NSTAGE) * HSTAGEB);
            #pragma unroll
            for (int p = 0; p < 2; p++)
                ldsm4(bk + (uint32_t)(p * 16 * HP * 2),
                      b[2 * p][0], b[2 * p][1], b[2 * p + 1][0], b[2 * p + 1][1]);
            #pragma unroll
            for (int ms = 0; ms < 2; ms++)
                #pragma unroll
                for (int ns = 0; ns < 4; ns++)
                    mma_f16(acc[ms][ns], a[ms], b[ns]);
        }
    };

    #pragma unroll 1
    for (int c = 0; c < 4; c++) {
        float accT[2][4][4];
        #pragma unroll
        for (int ms = 0; ms < 2; ms++)
            #pragma unroll
            for (int ns = 0; ns < 4; ns++)
                #pragma unroll
                for (int q = 0; q < 4; q++) accT[ms][ns][q] = 0.0f;

        run_gemm(hnS, Bt1 + (size_t)(c * 128) * DM, DM, accT);

        __syncthreads();
        const float* b1c = b1 + c * 128;
        #pragma unroll
        for (int ms = 0; ms < 2; ms++) {
            #pragma unroll
            for (int half = 0; half < 2; half++) {
                int r = warpm * 32 + ms * 16 + half * 8 + (lane >> 2);
                #pragma unroll
                for (int ns = 0; ns < 4; ns++) {
                    int cl = warpn * 32 + ns * 8 + (lane & 3) * 2;
                    float v0 = accT[ms][ns][half * 2 + 0] + __ldg(b1c + cl);
                    float v1 = accT[ms][ns][half * 2 + 1] + __ldg(b1c + cl + 1);
                    v0 = (v0 >= 0.0f) ? v0 : slp * v0;
                    v1 = (v1 >= 0.0f) ? v1 : slp * v1;
                    *(__half2*)&tHalf[r * FPH + cl] = __floats2half2_rn(v0, v1);
                }
            }
        }
        __syncthreads();

        run_gemm(tS, Bt2 + (size_t)(c * 128), DFFH, accO);
    }

    #pragma unroll
    for (int ms = 0; ms < 2; ms++) {
        #pragma unroll
        for (int half = 0; half < 2; half++) {
            int r = rowBase + warpm * 32 + ms * 16 + half * 8 + (lane >> 2);
            if (r >= NNODES) continue;
            #pragma unroll
            for (int ns = 0; ns < 4; ns++) {
                int cl = warpn * 32 + ns * 8 + (lane & 3) * 2;
                float2 hv = *(const float2*)&hres[(size_t)r * DM + cl];
                float v0 = accO[ms][ns][half * 2 + 0] + __ldg(b2 + cl)     + hv.x;
                float v1 = accO[ms][ns][half * 2 + 1] + __ldg(b2 + cl + 1) + hv.y;
                *(float2*)&Cout[(size_t)r * DM + cl] = make_float2(v0, v1);
                *(__half2*)&xr[(size_t)r * DM + cl] = __floats2half2_rn(v0, v1);
            }
        }
    }
}

// ---------------- batched transpose + fp16 convert (z = layer) ---------------
__global__ void transpose_h(const float* __restrict__ in, __half* __restrict__ out,
                            int K, int N)
{
    __shared__ float tile[32][33];
    size_t mat = (size_t)blockIdx.z * K * N;
    int k0 = blockIdx.x * 32, n0 = blockIdx.y * 32;
    int tx = threadIdx.x, ty = threadIdx.y;
    #pragma unroll
    for (int i = 0; i < 4; i++)
        tile[ty + i * 8][tx] = in[mat + (size_t)(k0 + ty + i * 8) * N + n0 + tx];
    __syncthreads();
    #pragma unroll
    for (int i = 0; i < 4; i++)
        out[mat + (size_t)(n0 + ty + i * 8) * K + k0 + tx] =
            __float2half_rn(tile[tx][ty + i * 8]);
}

// ---------------- convert layer-0 input to fp16 ------------------------------
__global__ void conv_half(const float* __restrict__ in, __half* __restrict__ out, int n4)
{
    int i = blockIdx.x * blockDim.x + threadIdx.x;
    if (i >= n4) return;
    float4 v = ((const float4*)in)[i];
    ((__half2*)out)[i * 2]     = __floats2half2_rn(v.x, v.y);
    ((__half2*)out)[i * 2 + 1] = __floats2half2_rn(v.z, v.w);
}

// ---------------- CSR build (once per call) ----------------------------------
__global__ void csr_zero()
{
    int i = blockIdx.x * blockDim.x + threadIdx.x;
    if (i <= NNODES) g_cnt[i] = 0;
}
__global__ void csr_hist(const int* __restrict__ dst)
{
    int e = blockIdx.x * blockDim.x + threadIdx.x;
    if (e < NEDGES) atomicAdd(&g_cnt[dst[e] + 1], 1);
}
__global__ void __launch_bounds__(1024) csr_scan()
{
    __shared__ int warpsum[32];
    const int T = 1024, TOT = NNODES + 1;
    const int ITEMS = (TOT + T - 1) / T;
    int t = threadIdx.x, lane = t & 31, w = t >> 5;
    int base = t * ITEMS;
    int sum = 0;
    for (int i = 0; i < ITEMS; i++) {
        int idx = base + i;
        if (idx < TOT) sum += g_cnt[idx];
    }
    int v = sum;
    #pragma unroll
    for (int o = 1; o < 32; o <<= 1) {
        int u = __shfl_up_sync(0xFFFFFFFFu, v, o);
        if (lane >= o) v += u;
    }
    if (lane == 31) warpsum[w] = v;
    __syncthreads();
    if (w == 0) {
        int wv = warpsum[lane];
        #pragma unroll
        for (int o = 1; o < 32; o <<= 1) {
            int u = __shfl_up_sync(0xFFFFFFFFu, wv, o);
            if (lane >= o) wv += u;
        }
        warpsum[lane] = wv;
    }
    __syncthreads();
    int excl = v - sum + (w > 0 ? warpsum[w - 1] : 0);
    int run = excl;
    for (int i = 0; i < ITEMS; i++) {
        int idx = base + i;
        if (idx < TOT) {
            run += g_cnt[idx];
            g_cnt[idx] = run;
            if (idx < NNODES) g_wo[idx] = run;
        }
    }
}
__global__ void csr_scatter(const int* __restrict__ src, const int* __restrict__ dst)
{
    int e = blockIdx.x * blockDim.x + threadIdx.x;
    if (e >= NEDGES) return;
    int d = dst[e];
    int pos = atomicAdd(&g_wo[d], 1);
    g_adj[pos] = src[e];
}

// ---------------- warp-per-node: softmax-agg + PReLU + 2x LayerNorm ----------
__global__ void __launch_bounds__(256) gat_agg_ln(
    const float* __restrict__ conv_bias, const float* __restrict__ a_conv,
    const float* __restrict__ ln_scale,  const float* __restrict__ ln_bias)
{
    int n = blockIdx.x * 8 + (threadIdx.x >> 5);
    if (n >= NNODES) return;
    int lane = threadIdx.x & 31;
    int h = lane >> 2;

    float myer = (lane < HH) ? g_er[n * HH + lane] : 0.0f;
    int beg = g_cnt[n], end = g_cnt[n + 1];

    float acc[4] = {0.f, 0.f, 0.f, 0.f};
    float den = 0.f;
    int i = beg;
    #pragma unroll 1
    for (; i + 2 <= end; i += 2) {
        int s0 = g_adj[i], s1 = g_adj[i + 1];
        float ex0 = 0.f, ex1 = 0.f;
        if (lane < HH) {
            float l0 = g_el[s0 * HH + lane] + myer;
            float l1 = g_el[s1 * HH + lane] + myer;
            l0 = (l0 >= 0.0f) ? l0 : 0.2f * l0;
            l1 = (l1 >= 0.0f) ? l1 : 0.2f * l1;
            ex0 = __expf(l0);
            ex1 = __expf(l1);
            den += ex0 + ex1;
        }
        float eb0 = __shfl_sync(0xFFFFFFFFu, ex0, h);
        float eb1 = __shfl_sync(0xFFFFFFFFu, ex1, h);
        uint2 r0 = *(const uint2*)&g_z[(size_t)s0 * DM + lane * 4];
        uint2 r1 = *(const uint2*)&g_z[(size_t)s1 * DM + lane * 4];
        float2 a0 = __half22float2(*(__half2*)&r0.x);
        float2 a1 = __half22float2(*(__half2*)&r0.y);
        float2 b0 = __half22float2(*(__half2*)&r1.x);
        float2 b1 = __half22float2(*(__half2*)&r1.y);
        acc[0] = fmaf(eb0, a0.x, acc[0]);
        acc[1] = fmaf(eb0, a0.y, acc[1]);
        acc[2] = fmaf(eb0, a1.x, acc[2]);
        acc[3] = fmaf(eb0, a1.y, acc[3]);
        acc[0] = fmaf(eb1, b0.x, acc[0]);
        acc[1] = fmaf(eb1, b0.y, acc[1]);
        acc[2] = fmaf(eb1, b1.x, acc[2]);
        acc[3] = fmaf(eb1, b1.y, acc[3]);
    }
    if (i < end) {
        int s = g_adj[i];
        float ex = 0.f;
        if (lane < HH) {
            float lg = g_el[s * HH + lane] + myer;
            lg = (lg >= 0.0f) ? lg : 0.2f * lg;
            ex = __expf(lg);
            den += ex;
        }
        float exb = __shfl_sync(0xFFFFFFFFu, ex, h);
        uint2 r0 = *(const uint2*)&g_z[(size_t)s * DM + lane * 4];
        float2 a0 = __half22float2(*(__half2*)&r0.x);
        float2 a1 = __half22float2(*(__half2*)&r0.y);
        acc[0] = fmaf(exb, a0.x, acc[0]);
        acc[1] = fmaf(exb, a0.y, acc[1]);
        acc[2] = fmaf(exb, a1.x, acc[2]);
        acc[3] = fmaf(exb, a1.y, acc[3]);
    }
    float denb = fmaxf(__shfl_sync(0xFFFFFFFFu, den, h), 1e-9f);

    int c = lane * 4;
    float4 cb = *(const float4*)&conv_bias[c];
    float a = __ldg(a_conv);
    float v[4] = {acc[0] / denb + cb.x, acc[1] / denb + cb.y,
                  acc[2] / denb + cb.z, acc[3] / denb + cb.w};
    #pragma unroll
    for (int q = 0; q < 4; q++) v[q] = (v[q] >= 0.0f) ? v[q] : a * v[q];

    float s = 0.f, s2 = 0.f;
    #pragma unroll
    for (int q = 0; q < 4; q++) { s += v[q]; s2 += v[q] * v[q]; }
    #pragma unroll
    for (int o = 16; o > 0; o >>= 1) {
        s  += __shfl_xor_sync(0xFFFFFFFFu, s, o);
        s2 += __shfl_xor_sync(0xFFFFFFFFu, s2, o);
    }
    float m = s * (1.0f / DM);
    float var = s2 * (1.0f / DM) - m * m;
    float inv = rsqrtf(var + 1e-5f);
    float4 lsc = *(const float4*)&ln_scale[c];
    float4 lbi = *(const float4*)&ln_bias[c];
    float hv[4];
    hv[0] = (v[0] - m) * inv * lsc.x + lbi.x;
    hv[1] = (v[1] - m) * inv * lsc.y + lbi.y;
    hv[2] = (v[2] - m) * inv * lsc.z + lbi.z;
    hv[3] = (v[3] - m) * inv * lsc.w + lbi.w;
    *(float4*)&g_h[(size_t)n * DM + c] = make_float4(hv[0], hv[1], hv[2], hv[3]);

    float t = 0.f, t2 = 0.f;
    #pragma unroll
    for (int q = 0; q < 4; q++) { t += hv[q]; t2 += hv[q] * hv[q]; }
    #pragma unroll
    for (int o = 16; o > 0; o >>= 1) {
        t  += __shfl_xor_sync(0xFFFFFFFFu, t, o);
        t2 += __shfl_xor_sync(0xFFFFFFFFu, t2, o);
    }
    float m2 = t * (1.0f / DM);
    float var2 = t2 * (1.0f / DM) - m2 * m2;
    float inv2 = rsqrtf(var2 + 1e-5f);
    float o0 = (hv[0] - m2) * inv2 * lsc.x + lbi.x;
    float o1 = (hv[1] - m2) * inv2 * lsc.y + lbi.y;
    float o2 = (hv[2] - m2) * inv2 * lsc.z + lbi.z;
    float o3 = (hv[3] - m2) * inv2 * lsc.w + lbi.w;
    *(__half2*)&g_hn[(size_t)n * DM + c]     = __floats2half2_rn(o0, o1);
    *(__half2*)&g_hn[(size_t)n * DM + c + 2] = __floats2half2_rn(o2, o3);
}

// ---------------- launcher ---------------------------------------------------
extern "C" void kernel_launch(void* const* d_in, const int* in_sizes, int n_in,
                              void* d_out, int out_size)
{
    const float* in_feats = (const float*)d_in[0];
    const int*   src      = (const int*)  d_in[1];
    const int*   dst      = (const int*)  d_in[2];
    const float* W        = (const float*)d_in[3];
    const float* attn_l   = (const float*)d_in[4];
    const float* attn_r   = (const float*)d_in[5];
    const float* conv_b   = (const float*)d_in[6];
    const float* a_conv   = (const float*)d_in[7];
    const float* ln_scale = (const float*)d_in[8];
    const float* ln_bias  = (const float*)d_in[9];
    const float* W1       = (const float*)d_in[10];
    const float* b1       = (const float*)d_in[11];
    const float* W2       = (const float*)d_in[12];
    const float* b2       = (const float*)d_in[13];
    const float* a_ff     = (const float*)d_in[14];
    float* out = (float*)d_out;

    float *hP;
    __half *zP, *xrP, *hnP, *btP;
    cudaGetSymbolAddress((void**)&zP,  g_z);
    cudaGetSymbolAddress((void**)&xrP, g_xr);
    cudaGetSymbolAddress((void**)&hP,  g_h);
    cudaGetSymbolAddress((void**)&hnP, g_hn);
    cudaGetSymbolAddress((void**)&btP, g_bt);

    cudaFuncSetAttribute(gemm_z, cudaFuncAttributeMaxDynamicSharedMemorySize, G0SMEM);
    cudaFuncSetAttribute(ff_fused, cudaFuncAttributeMaxDynamicSharedMemorySize, FF_SMEM);

    const int E_BLOCKS = (NEDGES + 255) / 256;
    const int RC_BLOCKS = (NNODES * DM / 4 + 255) / 256;

    // batched weight transposes -> fp16 (z = layer)
    transpose_h<<<dim3(DM / 32, DM / 32, 3), dim3(32, 8)>>>(W, btP + OFF_W(0), DM, DM);
    transpose_h<<<dim3(DM / 32, DFFH / 32, 3), dim3(32, 8)>>>(W1, btP + OFF_W1(0), DM, DFFH);
    transpose_h<<<dim3(DFFH / 32, DM / 32, 3), dim3(32, 8)>>>(W2, btP + OFF_W2(0), DFFH, DM);
    conv_half<<<RC_BLOCKS, 256>>>(in_feats, xrP, NNODES * DM / 4);

    // CSR build (graph fixed across layers)
    csr_zero<<<(NNODES + 256) / 256, 256>>>();
    csr_hist<<<E_BLOCKS, 256>>>(dst);
    csr_scan<<<1, 1024>>>();
    csr_scatter<<<E_BLOCKS, 256>>>(src, dst);

    for (int l = 0; l < LL; l++) {
        // z = xr @ W  (+ fused el/er)
        gemm_z<<<dim3(1, MTILES), 256, G0SMEM>>>(
            xrP, btP + OFF_W(l), zP,
            attn_l + (size_t)l * DM, attn_r + (size_t)l * DM);

        gat_agg_ln<<<(NNODES + 7) / 8, 256>>>(conv_b + (size_t)l * DM, a_conv + l,
                                              ln_scale + (size_t)l * DM,
                                              ln_bias + (size_t)l * DM);

        // out[l] = h + prelu(hn@W1+b1)@W2 + b2 ; xr = fp16(out[l])
        ff_fused<<<FTILES, 256, FF_SMEM>>>(
            hnP, btP + OFF_W1(l), btP + OFF_W2(l),
            b1 + (size_t)l * DFFH, a_ff + l, b2 + (size_t)l * DM,
            hP, out + (size_t)l * NNODES * DM, xrP);
    }
}

// round 13
// speedup vs baseline: 1.2973x; 1.2973x over previous
#include <cuda_runtime.h>
#include <cuda_fp16.h>
#include <math.h>
#include <stdint.h>

#define NNODES 50000
#define NEDGES 600000
#define DM 128
#define HH 8
#define DH 16
#define DFFH 512
#define LL 3
#define MTILES ((NNODES + 127) / 128)   // 391
#define FTILES ((NNODES + 63) / 64)     // 782

// ---------------- scratch (static device memory; no allocs allowed) --------
__device__ float  g_z [(size_t)NNODES * DM];     // fp32 projected features
__device__ __half g_xr[(size_t)NNODES * DM];     // fp16 layer input
__device__ float  g_el[(size_t)NNODES * HH];
__device__ float  g_er[(size_t)NNODES * HH];
__device__ float  g_h [(size_t)NNODES * DM];
__device__ __half g_hn[(size_t)NNODES * DM];     // fp16
__device__ __half g_bt[(size_t)3 * (DM * DM + DM * DFFH + DFFH * DM)]; // all W^T fp16
__device__ int    g_cnt[NNODES + 1];             // counts -> rowptr
__device__ int    g_wo [NNODES];                 // scatter write offsets
__device__ int    g_adj[NEDGES];                 // src ids grouped by dst

#define OFF_W(l)  ((size_t)(l) * DM * DM)
#define OFF_W1(l) ((size_t)3 * DM * DM + (size_t)(l) * DM * DFFH)
#define OFF_W2(l) ((size_t)3 * DM * DM + (size_t)3 * DM * DFFH + (size_t)(l) * DFFH * DM)

// ---------------- helpers ------------------------------------------------
__device__ __forceinline__ uint32_t smem_u32(const void* p) {
    uint32_t a;
    asm("{ .reg .u64 t; cvta.to.shared.u64 t, %1; cvt.u32.u64 %0, t; }" : "=r"(a) : "l"(p));
    return a;
}
__device__ __forceinline__ void cp_async16(uint32_t saddr, const void* gaddr, uint32_t sz) {
    asm volatile("cp.async.cg.shared.global [%0], [%1], 16, %2;"
                 :: "r"(saddr), "l"(gaddr), "r"(sz) : "memory");
}
// fp16 mma: D(f32) += A(f16, m16k16) * B(f16, k16n8)
__device__ __forceinline__ void mma_f16(float* c, const uint32_t* a, const uint32_t* b) {
    asm volatile("mma.sync.aligned.m16n8k16.row.col.f32.f16.f16.f32 "
                 "{%0,%1,%2,%3}, {%4,%5,%6,%7}, {%8,%9}, {%0,%1,%2,%3};"
                 : "+f"(c[0]), "+f"(c[1]), "+f"(c[2]), "+f"(c[3])
                 : "r"(a[0]), "r"(a[1]), "r"(a[2]), "r"(a[3]),
                   "r"(b[0]), "r"(b[1]));
}
__device__ __forceinline__ void ldsm4(uint32_t addr, uint32_t& r0, uint32_t& r1,
                                      uint32_t& r2, uint32_t& r3) {
    asm volatile("ldmatrix.sync.aligned.m8n8.x4.shared.b16 {%0,%1,%2,%3}, [%4];"
                 : "=r"(r0), "=r"(r1), "=r"(r2), "=r"(r3) : "r"(addr));
}

#define HP 24                              // halves per staged row (16 + 8 pad)
#define HSTAGEB (128 * HP * 2)             // 6144 bytes per matrix per k16 stage
#define NSTAGE 3
#define G0SMEM (2 * NSTAGE * HSTAGEB)      // 36864 bytes

// ---------------- fp16 mma GEMM: z-projection + fused el/er ------------------
// C[M x 128] = A[M x 128] @ Bt^T  (half inputs, fp32 out)
__global__ void __launch_bounds__(256, 2) gemm_z(
    const __half* __restrict__ A, const __half* __restrict__ Bt,
    float* __restrict__ C,
    const float* __restrict__ attn_l, const float* __restrict__ attn_r)
{
    extern __shared__ char smem_raw[];
    __shared__ float sAL[DM], sAR[DM];

    const int tid  = threadIdx.x;
    const int lane = tid & 31;
    const int wid  = tid >> 5;
    const int warpm = wid & 3;          // 4 warps along M (32 rows)
    const int warpn = wid >> 2;         // 2 warps along N (64 cols)
    const int rowBase = blockIdx.y * 128;

    if (tid < DM) { sAL[tid] = attn_l[tid]; sAR[tid] = attn_r[tid]; }
    __syncthreads();

    const uint32_t aS = smem_u32(smem_raw);
    const uint32_t bS = aS + NSTAGE * HSTAGEB;

    const uint32_t aBase = aS +
        (uint32_t)(((warpm * 32) + (((lane >> 3) & 1) * 8) + (lane & 7)) * HP
                   + (lane >> 4) * 8) * 2;
    const uint32_t bBase = bS +
        (uint32_t)(((warpn * 64) + (((lane >> 4) & 1) * 8) + (lane & 7)) * HP
                   + ((lane >> 3) & 1) * 8) * 2;

    auto load_stage = [&](int buf, int k0) {
        int row = tid >> 1;
        int kc  = (tid & 1) * 8;
        int gr = rowBase + row;
        cp_async16(aS + (uint32_t)(row * HP + kc) * 2 + buf * HSTAGEB,
                   A + (size_t)(gr < NNODES ? gr : 0) * DM + k0 + kc,
                   (gr < NNODES) ? 16u : 0u);
        cp_async16(bS + (uint32_t)(row * HP + kc) * 2 + buf * HSTAGEB,
                   Bt + (size_t)row * DM + k0 + kc, 16u);
        asm volatile("cp.async.commit_group;" ::: "memory");
    };

    float acc[2][8][4];
    #pragma unroll
    for (int ms = 0; ms < 2; ms++)
        #pragma unroll
        for (int ns = 0; ns < 8; ns++)
            #pragma unroll
            for (int q = 0; q < 4; q++) acc[ms][ns][q] = 0.0f;

    load_stage(0, 0);
    load_stage(1, 16);

    #pragma unroll
    for (int kt = 0; kt < 8; ++kt) {
        if (kt + 1 < 8) asm volatile("cp.async.wait_group 1;" ::: "memory");
        else            asm volatile("cp.async.wait_group 0;" ::: "memory");
        __syncthreads();
        if (kt + 2 < 8) load_stage((kt + 2) % NSTAGE, (kt + 2) * 16);

        const uint32_t kOff = (uint32_t)((kt % NSTAGE) * HSTAGEB);
        uint32_t a[2][4], b[8][2];
        ldsm4(aBase + kOff, a[0][0], a[0][1], a[0][2], a[0][3]);
        ldsm4(aBase + kOff + 16 * HP * 2, a[1][0], a[1][1], a[1][2], a[1][3]);
        #pragma unroll
        for (int p = 0; p < 4; p++)
            ldsm4(bBase + kOff + (uint32_t)(p * 16 * HP * 2),
                  b[2 * p][0], b[2 * p][1], b[2 * p + 1][0], b[2 * p + 1][1]);
        #pragma unroll
        for (int ms = 0; ms < 2; ms++)
            #pragma unroll
            for (int ns = 0; ns < 8; ns++)
                mma_f16(acc[ms][ns], a[ms], b[ns]);
    }

    // epilogue: store z (fp32) + fused el/er
    #pragma unroll
    for (int ms = 0; ms < 2; ms++) {
        #pragma unroll
        for (int half = 0; half < 2; half++) {
            int r = rowBase + warpm * 32 + ms * 16 + half * 8 + (lane >> 2);
            const bool valid = (r < NNODES);
            float psl[4], psr[4];
            #pragma unroll
            for (int q = 0; q < 4; q++) { psl[q] = 0.f; psr[q] = 0.f; }
            #pragma unroll
            for (int ns = 0; ns < 8; ns++) {
                int cl = warpn * 64 + ns * 8 + (lane & 3) * 2;
                float v0 = acc[ms][ns][half * 2 + 0];
                float v1 = acc[ms][ns][half * 2 + 1];
                if (valid)
                    *(float2*)&C[(size_t)r * DM + cl] = make_float2(v0, v1);
                int hh = ns >> 1;
                psl[hh] += v0 * sAL[cl] + v1 * sAL[cl + 1];
                psr[hh] += v0 * sAR[cl] + v1 * sAR[cl + 1];
            }
            #pragma unroll
            for (int d = 1; d <= 2; d <<= 1) {
                #pragma unroll
                for (int q = 0; q < 4; q++) {
                    psl[q] += __shfl_xor_sync(0xFFFFFFFFu, psl[q], d);
                    psr[q] += __shfl_xor_sync(0xFFFFFFFFu, psr[q], d);
                }
            }
            if ((lane & 3) == 0 && valid) {
                #pragma unroll
                for (int q = 0; q < 4; q++) {
                    int hidx = r * HH + warpn * 4 + q;
                    g_el[hidx] = psl[q];
                    g_er[hidx] = psr[q];
                }
            }
        }
    }
}

// ---------------- fused FeedForward (fp16): 64-row blocks --------------------
#define FPH 136
#define FF_A (64 * FPH * 2)
#define FF_SMEM (2 * FF_A + NSTAGE * HSTAGEB)

__global__ void __launch_bounds__(256, 2) ff_fused(
    const __half* __restrict__ hn, const __half* __restrict__ Bt1,
    const __half* __restrict__ Bt2,
    const float* __restrict__ b1, const float* __restrict__ slope,
    const float* __restrict__ b2, const float* __restrict__ hres,
    float* __restrict__ Cout, __half* __restrict__ xr)
{
    extern __shared__ char smem_raw[];
    const int tid  = threadIdx.x;
    const int lane = tid & 31;
    const int wid  = tid >> 5;
    const int warpm = wid & 1;
    const int warpn = wid >> 1;
    const int rowBase = blockIdx.x * 64;

    const uint32_t hnS = smem_u32(smem_raw);
    const uint32_t tS  = hnS + FF_A;
    const uint32_t bS  = tS + FF_A;
    __half* tHalf = (__half*)(smem_raw + FF_A);

    const uint32_t aLane =
        (uint32_t)(((warpm * 32) + (((lane >> 3) & 1) * 8) + (lane & 7)) * FPH
                   + (lane >> 4) * 8) * 2;
    const uint32_t bLane =
        (uint32_t)(((warpn * 32) + (((lane >> 4) & 1) * 8) + (lane & 7)) * HP
                   + ((lane >> 3) & 1) * 8) * 2;

    #pragma unroll
    for (int i = 0; i < 4; i++) {
        int chunk = tid + i * 256;
        int m = chunk >> 4;
        int q = (chunk & 15) * 8;
        int gr = rowBase + m;
        cp_async16(hnS + (uint32_t)(m * FPH + q) * 2,
                   hn + (size_t)(gr < NNODES ? gr : 0) * DM + q,
                   (gr < NNODES) ? 16u : 0u);
    }
    asm volatile("cp.async.commit_group;" ::: "memory");

    float accO[2][4][4];
    #pragma unroll
    for (int ms = 0; ms < 2; ms++)
        #pragma unroll
        for (int ns = 0; ns < 4; ns++)
            #pragma unroll
            for (int q = 0; q < 4; q++) accO[ms][ns][q] = 0.0f;

    const float slp = __ldg(slope);

    auto run_gemm = [&](uint32_t aSm, const __half* Bbase, int bstr,
                        float (*acc)[4][4]) {
        auto loadB = [&](int buf, int kt) {
            int row = tid >> 1;
            int kq  = (tid & 1) * 8;
            cp_async16(bS + (uint32_t)(row * HP + kq) * 2 + buf * HSTAGEB,
                       Bbase + (size_t)row * bstr + kt * 16 + kq, 16u);
            asm volatile("cp.async.commit_group;" ::: "memory");
        };
        __syncthreads();
        loadB(0, 0);
        loadB(1, 1);
        #pragma unroll
        for (int kt = 0; kt < 8; kt++) {
            if (kt + 1 < 8) asm volatile("cp.async.wait_group 1;" ::: "memory");
            else            asm volatile("cp.async.wait_group 0;" ::: "memory");
            __syncthreads();
            if (kt + 2 < 8) loadB((kt + 2) % NSTAGE, kt + 2);

            uint32_t a[2][4], b[4][2];
            const uint32_t ak = aSm + aLane + (uint32_t)(kt * 16) * 2;
            ldsm4(ak, a[0][0], a[0][1], a[0][2], a[0][3]);
            ldsm4(ak + 16 * FPH * 2, a[1][0], a[1][1], a[1][2], a[1][3]);
            const uint32_t bk = bS + bLane + (uint32_t)((kt % NSTAGE) * HSTAGEB);
            #pragma unroll
            for (int p = 0; p < 2; p++)
                ldsm4(bk + (uint32_t)(p * 16 * HP * 2),
                      b[2 * p][0], b[2 * p][1], b[2 * p + 1][0], b[2 * p + 1][1]);
            #pragma unroll
            for (int ms = 0; ms < 2; ms++)
                #pragma unroll
                for (int ns = 0; ns < 4; ns++)
                    mma_f16(acc[ms][ns], a[ms], b[ns]);
        }
    };

    #pragma unroll 1
    for (int c = 0; c < 4; c++) {
        float accT[2][4][4];
        #pragma unroll
        for (int ms = 0; ms < 2; ms++)
            #pragma unroll
            for (int ns = 0; ns < 4; ns++)
                #pragma unroll
                for (int q = 0; q < 4; q++) accT[ms][ns][q] = 0.0f;

        run_gemm(hnS, Bt1 + (size_t)(c * 128) * DM, DM, accT);

        __syncthreads();
        const float* b1c = b1 + c * 128;
        #pragma unroll
        for (int ms = 0; ms < 2; ms++) {
            #pragma unroll
            for (int half = 0; half < 2; half++) {
                int r = warpm * 32 + ms * 16 + half * 8 + (lane >> 2);
                #pragma unroll
                for (int ns = 0; ns < 4; ns++) {
                    int cl = warpn * 32 + ns * 8 + (lane & 3) * 2;
                    float v0 = accT[ms][ns][half * 2 + 0] + __ldg(b1c + cl);
                    float v1 = accT[ms][ns][half * 2 + 1] + __ldg(b1c + cl + 1);
                    v0 = (v0 >= 0.0f) ? v0 : slp * v0;
                    v1 = (v1 >= 0.0f) ? v1 : slp * v1;
                    *(__half2*)&tHalf[r * FPH + cl] = __floats2half2_rn(v0, v1);
                }
            }
        }
        __syncthreads();

        run_gemm(tS, Bt2 + (size_t)(c * 128), DFFH, accO);
    }

    #pragma unroll
    for (int ms = 0; ms < 2; ms++) {
        #pragma unroll
        for (int half = 0; half < 2; half++) {
            int r = rowBase + warpm * 32 + ms * 16 + half * 8 + (lane >> 2);
            if (r >= NNODES) continue;
            #pragma unroll
            for (int ns = 0; ns < 4; ns++) {
                int cl = warpn * 32 + ns * 8 + (lane & 3) * 2;
                float2 hv = *(const float2*)&hres[(size_t)r * DM + cl];
                float v0 = accO[ms][ns][half * 2 + 0] + __ldg(b2 + cl)     + hv.x;
                float v1 = accO[ms][ns][half * 2 + 1] + __ldg(b2 + cl + 1) + hv.y;
                *(float2*)&Cout[(size_t)r * DM + cl] = make_float2(v0, v1);
                *(__half2*)&xr[(size_t)r * DM + cl] = __floats2half2_rn(v0, v1);
            }
        }
    }
}

// ---------------- batched transpose + fp16 convert (z = layer) ---------------
__global__ void transpose_h(const float* __restrict__ in, __half* __restrict__ out,
                            int K, int N)
{
    __shared__ float tile[32][33];
    size_t mat = (size_t)blockIdx.z * K * N;
    int k0 = blockIdx.x * 32, n0 = blockIdx.y * 32;
    int tx = threadIdx.x, ty = threadIdx.y;
    #pragma unroll
    for (int i = 0; i < 4; i++)
        tile[ty + i * 8][tx] = in[mat + (size_t)(k0 + ty + i * 8) * N + n0 + tx];
    __syncthreads();
    #pragma unroll
    for (int i = 0; i < 4; i++)
        out[mat + (size_t)(n0 + ty + i * 8) * K + k0 + tx] =
            __float2half_rn(tile[tx][ty + i * 8]);
}

// ---------------- convert layer-0 input to fp16 ------------------------------
__global__ void conv_half(const float* __restrict__ in, __half* __restrict__ out, int n4)
{
    int i = blockIdx.x * blockDim.x + threadIdx.x;
    if (i >= n4) return;
    float4 v = ((const float4*)in)[i];
    ((__half2*)out)[i * 2]     = __floats2half2_rn(v.x, v.y);
    ((__half2*)out)[i * 2 + 1] = __floats2half2_rn(v.z, v.w);
}

// ---------------- CSR build (once per call) ----------------------------------
__global__ void csr_zero()
{
    int i = blockIdx.x * blockDim.x + threadIdx.x;
    if (i <= NNODES) g_cnt[i] = 0;
}
__global__ void csr_hist(const int* __restrict__ dst)
{
    int e = blockIdx.x * blockDim.x + threadIdx.x;
    if (e < NEDGES) atomicAdd(&g_cnt[dst[e] + 1], 1);
}
__global__ void __launch_bounds__(1024) csr_scan()
{
    __shared__ int warpsum[32];
    const int T = 1024, TOT = NNODES + 1;
    const int ITEMS = (TOT + T - 1) / T;
    int t = threadIdx.x, lane = t & 31, w = t >> 5;
    int base = t * ITEMS;
    int sum = 0;
    for (int i = 0; i < ITEMS; i++) {
        int idx = base + i;
        if (idx < TOT) sum += g_cnt[idx];
    }
    int v = sum;
    #pragma unroll
    for (int o = 1; o < 32; o <<= 1) {
        int u = __shfl_up_sync(0xFFFFFFFFu, v, o);
        if (lane >= o) v += u;
    }
    if (lane == 31) warpsum[w] = v;
    __syncthreads();
    if (w == 0) {
        int wv = warpsum[lane];
        #pragma unroll
        for (int o = 1; o < 32; o <<= 1) {
            int u = __shfl_up_sync(0xFFFFFFFFu, wv, o);
            if (lane >= o) wv += u;
        }
        warpsum[lane] = wv;
    }
    __syncthreads();
    int excl = v - sum + (w > 0 ? warpsum[w - 1] : 0);
    int run = excl;
    for (int i = 0; i < ITEMS; i++) {
        int idx = base + i;
        if (idx < TOT) {
            run += g_cnt[idx];
            g_cnt[idx] = run;
            if (idx < NNODES) g_wo[idx] = run;
        }
    }
}
__global__ void csr_scatter(const int* __restrict__ src, const int* __restrict__ dst)
{
    int e = blockIdx.x * blockDim.x + threadIdx.x;
    if (e >= NEDGES) return;
    int d = dst[e];
    int pos = atomicAdd(&g_wo[d], 1);
    g_adj[pos] = src[e];
}

// ---------------- warp-per-node: softmax-agg + PReLU + 2x LayerNorm ----------
__global__ void __launch_bounds__(256) gat_agg_ln(
    const float* __restrict__ conv_bias, const float* __restrict__ a_conv,
    const float* __restrict__ ln_scale,  const float* __restrict__ ln_bias)
{
    int n = blockIdx.x * 8 + (threadIdx.x >> 5);
    if (n >= NNODES) return;
    int lane = threadIdx.x & 31;
    int h = lane >> 2;

    float myer = (lane < HH) ? g_er[n * HH + lane] : 0.0f;
    int beg = g_cnt[n], end = g_cnt[n + 1];

    float acc[4] = {0.f, 0.f, 0.f, 0.f};
    float den = 0.f;
    int i = beg;
    #pragma unroll 1
    for (; i + 4 <= end; i += 4) {
        int s0 = g_adj[i],     s1 = g_adj[i + 1];
        int s2 = g_adj[i + 2], s3 = g_adj[i + 3];
        float ex0 = 0.f, ex1 = 0.f, ex2 = 0.f, ex3 = 0.f;
        if (lane < HH) {
            float l0 = g_el[s0 * HH + lane] + myer;
            float l1 = g_el[s1 * HH + lane] + myer;
            float l2 = g_el[s2 * HH + lane] + myer;
            float l3 = g_el[s3 * HH + lane] + myer;
            l0 = (l0 >= 0.0f) ? l0 : 0.2f * l0;
            l1 = (l1 >= 0.0f) ? l1 : 0.2f * l1;
            l2 = (l2 >= 0.0f) ? l2 : 0.2f * l2;
            l3 = (l3 >= 0.0f) ? l3 : 0.2f * l3;
            ex0 = __expf(l0); ex1 = __expf(l1);
            ex2 = __expf(l2); ex3 = __expf(l3);
            den += (ex0 + ex1) + (ex2 + ex3);
        }
        float eb0 = __shfl_sync(0xFFFFFFFFu, ex0, h);
        float eb1 = __shfl_sync(0xFFFFFFFFu, ex1, h);
        float eb2 = __shfl_sync(0xFFFFFFFFu, ex2, h);
        float eb3 = __shfl_sync(0xFFFFFFFFu, ex3, h);
        float4 z0 = *(const float4*)&g_z[(size_t)s0 * DM + lane * 4];
        float4 z1 = *(const float4*)&g_z[(size_t)s1 * DM + lane * 4];
        float4 z2 = *(const float4*)&g_z[(size_t)s2 * DM + lane * 4];
        float4 z3 = *(const float4*)&g_z[(size_t)s3 * DM + lane * 4];
        acc[0] = fmaf(eb0, z0.x, acc[0]); acc[1] = fmaf(eb0, z0.y, acc[1]);
        acc[2] = fmaf(eb0, z0.z, acc[2]); acc[3] = fmaf(eb0, z0.w, acc[3]);
        acc[0] = fmaf(eb1, z1.x, acc[0]); acc[1] = fmaf(eb1, z1.y, acc[1]);
        acc[2] = fmaf(eb1, z1.z, acc[2]); acc[3] = fmaf(eb1, z1.w, acc[3]);
        acc[0] = fmaf(eb2, z2.x, acc[0]); acc[1] = fmaf(eb2, z2.y, acc[1]);
        acc[2] = fmaf(eb2, z2.z, acc[2]); acc[3] = fmaf(eb2, z2.w, acc[3]);
        acc[0] = fmaf(eb3, z3.x, acc[0]); acc[1] = fmaf(eb3, z3.y, acc[1]);
        acc[2] = fmaf(eb3, z3.z, acc[2]); acc[3] = fmaf(eb3, z3.w, acc[3]);
    }
    #pragma unroll 1
    for (; i < end; i++) {
        int s = g_adj[i];
        float ex = 0.f;
        if (lane < HH) {
            float lg = g_el[s * HH + lane] + myer;
            lg = (lg >= 0.0f) ? lg : 0.2f * lg;
            ex = __expf(lg);
            den += ex;
        }
        float exb = __shfl_sync(0xFFFFFFFFu, ex, h);
        float4 zv = *(const float4*)&g_z[(size_t)s * DM + lane * 4];
        acc[0] = fmaf(exb, zv.x, acc[0]);
        acc[1] = fmaf(exb, zv.y, acc[1]);
        acc[2] = fmaf(exb, zv.z, acc[2]);
        acc[3] = fmaf(exb, zv.w, acc[3]);
    }
    float denb = fmaxf(__shfl_sync(0xFFFFFFFFu, den, h), 1e-9f);

    int c = lane * 4;
    float4 cb = *(const float4*)&conv_bias[c];
    float a = __ldg(a_conv);
    float v[4] = {acc[0] / denb + cb.x, acc[1] / denb + cb.y,
                  acc[2] / denb + cb.z, acc[3] / denb + cb.w};
    #pragma unroll
    for (int q = 0; q < 4; q++) v[q] = (v[q] >= 0.0f) ? v[q] : a * v[q];

    float s = 0.f, s2 = 0.f;
    #pragma unroll
    for (int q = 0; q < 4; q++) { s += v[q]; s2 += v[q] * v[q]; }
    #pragma unroll
    for (int o = 16; o > 0; o >>= 1) {
        s  += __shfl_xor_sync(0xFFFFFFFFu, s, o);
        s2 += __shfl_xor_sync(0xFFFFFFFFu, s2, o);
    }
    float m = s * (1.0f / DM);
    float var = s2 * (1.0f / DM) - m * m;
    float inv = rsqrtf(var + 1e-5f);
    float4 lsc = *(const float4*)&ln_scale[c];
    float4 lbi = *(const float4*)&ln_bias[c];
    float hv[4];
    hv[0] = (v[0] - m) * inv * lsc.x + lbi.x;
    hv[1] = (v[1] - m) * inv * lsc.y + lbi.y;
    hv[2] = (v[2] - m) * inv * lsc.z + lbi.z;
    hv[3] = (v[3] - m) * inv * lsc.w + lbi.w;
    *(float4*)&g_h[(size_t)n * DM + c] = make_float4(hv[0], hv[1], hv[2], hv[3]);

    float t = 0.f, t2 = 0.f;
    #pragma unroll
    for (int q = 0; q < 4; q++) { t += hv[q]; t2 += hv[q] * hv[q]; }
    #pragma unroll
    for (int o = 16; o > 0; o >>= 1) {
        t  += __shfl_xor_sync(0xFFFFFFFFu, t, o);
        t2 += __shfl_xor_sync(0xFFFFFFFFu, t2, o);
    }
    float m2 = t * (1.0f / DM);
    float var2 = t2 * (1.0f / DM) - m2 * m2;
    float inv2 = rsqrtf(var2 + 1e-5f);
    float o0 = (hv[0] - m2) * inv2 * lsc.x + lbi.x;
    float o1 = (hv[1] - m2) * inv2 * lsc.y + lbi.y;
    float o2 = (hv[2] - m2) * inv2 * lsc.z + lbi.z;
    float o3 = (hv[3] - m2) * inv2 * lsc.w + lbi.w;
    *(__half2*)&g_hn[(size_t)n * DM + c]     = __floats2half2_rn(o0, o1);
    *(__half2*)&g_hn[(size_t)n * DM + c + 2] = __floats2half2_rn(o2, o3);
}

// ---------------- launcher ---------------------------------------------------
extern "C" void kernel_launch(void* const* d_in, const int* in_sizes, int n_in,
                              void* d_out, int out_size)
{
    const float* in_feats = (const float*)d_in[0];
    const int*   src      = (const int*)  d_in[1];
    const int*   dst      = (const int*)  d_in[2];
    const float* W        = (const float*)d_in[3];
    const float* attn_l   = (const float*)d_in[4];
    const float* attn_r   = (const float*)d_in[5];
    const float* conv_b   = (const float*)d_in[6];
    const float* a_conv   = (const float*)d_in[7];
    const float* ln_scale = (const float*)d_in[8];
    const float* ln_bias  = (const float*)d_in[9];
    const float* W1       = (const float*)d_in[10];
    const float* b1       = (const float*)d_in[11];
    const float* W2       = (const float*)d_in[12];
    const float* b2       = (const float*)d_in[13];
    const float* a_ff     = (const float*)d_in[14];
    float* out = (float*)d_out;

    float *zP, *hP;
    __half *xrP, *hnP, *btP;
    cudaGetSymbolAddress((void**)&zP,  g_z);
    cudaGetSymbolAddress((void**)&xrP, g_xr);
    cudaGetSymbolAddress((void**)&hP,  g_h);
    cudaGetSymbolAddress((void**)&hnP, g_hn);
    cudaGetSymbolAddress((void**)&btP, g_bt);

    cudaFuncSetAttribute(gemm_z, cudaFuncAttributeMaxDynamicSharedMemorySize, G0SMEM);
    cudaFuncSetAttribute(ff_fused, cudaFuncAttributeMaxDynamicSharedMemorySize, FF_SMEM);

    const int E_BLOCKS = (NEDGES + 255) / 256;
    const int RC_BLOCKS = (NNODES * DM / 4 + 255) / 256;

    // batched weight transposes -> fp16 (z = layer)
    transpose_h<<<dim3(DM / 32, DM / 32, 3), dim3(32, 8)>>>(W, btP + OFF_W(0), DM, DM);
    transpose_h<<<dim3(DM / 32, DFFH / 32, 3), dim3(32, 8)>>>(W1, btP + OFF_W1(0), DM, DFFH);
    transpose_h<<<dim3(DFFH / 32, DM / 32, 3), dim3(32, 8)>>>(W2, btP + OFF_W2(0), DFFH, DM);
    conv_half<<<RC_BLOCKS, 256>>>(in_feats, xrP, NNODES * DM / 4);

    // CSR build (graph fixed across layers)
    csr_zero<<<(NNODES + 256) / 256, 256>>>();
    csr_hist<<<E_BLOCKS, 256>>>(dst);
    csr_scan<<<1, 1024>>>();
    csr_scatter<<<E_BLOCKS, 256>>>(src, dst);

    for (int l = 0; l < LL; l++) {
        // z = xr @ W  (+ fused el/er)
        gemm_z<<<dim3(1, MTILES), 256, G0SMEM>>>(
            xrP, btP + OFF_W(l), zP,
            attn_l + (size_t)l * DM, attn_r + (size_t)l * DM);

        gat_agg_ln<<<(NNODES + 7) / 8, 256>>>(conv_b + (size_t)l * DM, a_conv + l,
                                              ln_scale + (size_t)l * DM,
                                              ln_bias + (size_t)l * DM);

        // out[l] = h + prelu(hn@W1+b1)@W2 + b2 ; xr = fp16(out[l])
        ff_fused<<<FTILES, 256, FF_SMEM>>>(
            hnP, btP + OFF_W1(l), btP + OFF_W2(l),
            b1 + (size_t)l * DFFH, a_ff + l, b2 + (size_t)l * DM,
            hP, out + (size_t)l * NNODES * DM, xrP);
    }
}

// round 14
// speedup vs baseline: 1.3891x; 1.0708x over previous
#include <cuda_runtime.h>
#include <cuda_fp16.h>
#include <math.h>
#include <stdint.h>

#define NNODES 50000
#define NEDGES 600000
#define DM 128
#define HH 8
#define DH 16
#define DFFH 512
#define LL 3
#define MTILES ((NNODES + 127) / 128)   // 391
#define FTILES ((NNODES + 63) / 64)     // 782

// ---------------- scratch (static device memory; no allocs allowed) --------
__device__ float  g_z [(size_t)NNODES * DM];     // fp32 projected features
__device__ __half g_xr[(size_t)NNODES * DM];     // fp16 layer input
__device__ float  g_el[(size_t)NNODES * HH];
__device__ float  g_er[(size_t)NNODES * HH];
__device__ float  g_h [(size_t)NNODES * DM];
__device__ __half g_hn[(size_t)NNODES * DM];     // fp16
__device__ __half g_bt[(size_t)3 * (DM * DM + DM * DFFH + DFFH * DM)]; // all W^T fp16
__device__ int    g_cnt[NNODES + 1];             // counts -> rowptr
__device__ int    g_wo [NNODES];                 // scatter write offsets
__device__ int    g_adj[NEDGES];                 // src ids grouped by dst

#define OFF_W(l)  ((size_t)(l) * DM * DM)
#define OFF_W1(l) ((size_t)3 * DM * DM + (size_t)(l) * DM * DFFH)
#define OFF_W2(l) ((size_t)3 * DM * DM + (size_t)3 * DM * DFFH + (size_t)(l) * DFFH * DM)

// ---------------- helpers ------------------------------------------------
__device__ __forceinline__ uint32_t smem_u32(const void* p) {
    uint32_t a;
    asm("{ .reg .u64 t; cvta.to.shared.u64 t, %1; cvt.u32.u64 %0, t; }" : "=r"(a) : "l"(p));
    return a;
}
__device__ __forceinline__ void cp_async16(uint32_t saddr, const void* gaddr, uint32_t sz) {
    asm volatile("cp.async.cg.shared.global [%0], [%1], 16, %2;"
                 :: "r"(saddr), "l"(gaddr), "r"(sz) : "memory");
}
// fp16 mma: D(f32) += A(f16, m16k16) * B(f16, k16n8)
__device__ __forceinline__ void mma_f16(float* c, const uint32_t* a, const uint32_t* b) {
    asm volatile("mma.sync.aligned.m16n8k16.row.col.f32.f16.f16.f32 "
                 "{%0,%1,%2,%3}, {%4,%5,%6,%7}, {%8,%9}, {%0,%1,%2,%3};"
                 : "+f"(c[0]), "+f"(c[1]), "+f"(c[2]), "+f"(c[3])
                 : "r"(a[0]), "r"(a[1]), "r"(a[2]), "r"(a[3]),
                   "r"(b[0]), "r"(b[1]));
}
__device__ __forceinline__ void ldsm4(uint32_t addr, uint32_t& r0, uint32_t& r1,
                                      uint32_t& r2, uint32_t& r3) {
    asm volatile("ldmatrix.sync.aligned.m8n8.x4.shared.b16 {%0,%1,%2,%3}, [%4];"
                 : "=r"(r0), "=r"(r1), "=r"(r2), "=r"(r3) : "r"(addr));
}

#define HP 40                              // halves per staged row (32 + 8 pad)
#define HSTAGEB (128 * HP * 2)             // 10240 bytes per matrix per k32 stage
#define NSTAGE 3
#define G0SMEM (2 * NSTAGE * HSTAGEB)      // 61440 bytes

// ---------------- fp16 mma GEMM: z-projection + fused el/er ------------------
// C[M x 128] = A[M x 128] @ Bt^T  (half inputs, fp32 out)
__global__ void __launch_bounds__(256, 2) gemm_z(
    const __half* __restrict__ A, const __half* __restrict__ Bt,
    float* __restrict__ C,
    const float* __restrict__ attn_l, const float* __restrict__ attn_r)
{
    extern __shared__ char smem_raw[];
    __shared__ float sAL[DM], sAR[DM];

    const int tid  = threadIdx.x;
    const int lane = tid & 31;
    const int wid  = tid >> 5;
    const int warpm = wid & 3;          // 4 warps along M (32 rows)
    const int warpn = wid >> 2;         // 2 warps along N (64 cols)
    const int rowBase = blockIdx.y * 128;

    if (tid < DM) { sAL[tid] = attn_l[tid]; sAR[tid] = attn_r[tid]; }
    __syncthreads();

    const uint32_t aS = smem_u32(smem_raw);
    const uint32_t bS = aS + NSTAGE * HSTAGEB;

    const uint32_t aBase = aS +
        (uint32_t)(((warpm * 32) + (((lane >> 3) & 1) * 8) + (lane & 7)) * HP
                   + (lane >> 4) * 8) * 2;
    const uint32_t bBase = bS +
        (uint32_t)(((warpn * 64) + (((lane >> 4) & 1) * 8) + (lane & 7)) * HP
                   + ((lane >> 3) & 1) * 8) * 2;

    // one K32 stage: 128 rows x 32 halves each for A and Bt
    auto load_stage = [&](int buf, int k0) {
        #pragma unroll
        for (int i = 0; i < 2; i++) {
            int c = tid + i * 256;           // 0..511
            int row = c >> 2;                // 0..127
            int kq  = (c & 3) * 8;           // 0,8,16,24 halves
            uint32_t soff = (uint32_t)(row * HP + kq) * 2 + buf * HSTAGEB;
            int gr = rowBase + row;
            cp_async16(aS + soff,
                       A + (size_t)(gr < NNODES ? gr : 0) * DM + k0 + kq,
                       (gr < NNODES) ? 16u : 0u);
            cp_async16(bS + soff,
                       Bt + (size_t)row * DM + k0 + kq, 16u);
        }
        asm volatile("cp.async.commit_group;" ::: "memory");
    };

    float acc[2][8][4];
    #pragma unroll
    for (int ms = 0; ms < 2; ms++)
        #pragma unroll
        for (int ns = 0; ns < 8; ns++)
            #pragma unroll
            for (int q = 0; q < 4; q++) acc[ms][ns][q] = 0.0f;

    load_stage(0, 0);
    load_stage(1, 32);

    #pragma unroll
    for (int kt = 0; kt < 4; ++kt) {
        if (kt + 1 < 4) asm volatile("cp.async.wait_group 1;" ::: "memory");
        else            asm volatile("cp.async.wait_group 0;" ::: "memory");
        __syncthreads();
        if (kt + 2 < 4) load_stage((kt + 2) % NSTAGE, (kt + 2) * 32);

        const uint32_t sOff = (uint32_t)((kt % NSTAGE) * HSTAGEB);
        #pragma unroll
        for (int sub = 0; sub < 2; sub++) {
            const uint32_t kOff = sOff + sub * 32;   // sub*16 halves
            uint32_t a[2][4], b[8][2];
            ldsm4(aBase + kOff, a[0][0], a[0][1], a[0][2], a[0][3]);
            ldsm4(aBase + kOff + 16 * HP * 2, a[1][0], a[1][1], a[1][2], a[1][3]);
            #pragma unroll
            for (int p = 0; p < 4; p++)
                ldsm4(bBase + kOff + (uint32_t)(p * 16 * HP * 2),
                      b[2 * p][0], b[2 * p][1], b[2 * p + 1][0], b[2 * p + 1][1]);
            #pragma unroll
            for (int ms = 0; ms < 2; ms++)
                #pragma unroll
                for (int ns = 0; ns < 8; ns++)
                    mma_f16(acc[ms][ns], a[ms], b[ns]);
        }
    }

    // epilogue: store z (fp32) + fused el/er
    #pragma unroll
    for (int ms = 0; ms < 2; ms++) {
        #pragma unroll
        for (int half = 0; half < 2; half++) {
            int r = rowBase + warpm * 32 + ms * 16 + half * 8 + (lane >> 2);
            const bool valid = (r < NNODES);
            float psl[4], psr[4];
            #pragma unroll
            for (int q = 0; q < 4; q++) { psl[q] = 0.f; psr[q] = 0.f; }
            #pragma unroll
            for (int ns = 0; ns < 8; ns++) {
                int cl = warpn * 64 + ns * 8 + (lane & 3) * 2;
                float v0 = acc[ms][ns][half * 2 + 0];
                float v1 = acc[ms][ns][half * 2 + 1];
                if (valid)
                    *(float2*)&C[(size_t)r * DM + cl] = make_float2(v0, v1);
                int hh = ns >> 1;
                psl[hh] += v0 * sAL[cl] + v1 * sAL[cl + 1];
                psr[hh] += v0 * sAR[cl] + v1 * sAR[cl + 1];
            }
            #pragma unroll
            for (int d = 1; d <= 2; d <<= 1) {
                #pragma unroll
                for (int q = 0; q < 4; q++) {
                    psl[q] += __shfl_xor_sync(0xFFFFFFFFu, psl[q], d);
                    psr[q] += __shfl_xor_sync(0xFFFFFFFFu, psr[q], d);
                }
            }
            if ((lane & 3) == 0 && valid) {
                #pragma unroll
                for (int q = 0; q < 4; q++) {
                    int hidx = r * HH + warpn * 4 + q;
                    g_el[hidx] = psl[q];
                    g_er[hidx] = psr[q];
                }
            }
        }
    }
}

// ---------------- fused FeedForward (fp16): 64-row blocks --------------------
#define FPH 136
#define FF_A (64 * FPH * 2)
#define FF_SMEM (2 * FF_A + NSTAGE * HSTAGEB)    // 34816 + 30720 = 65536

__global__ void __launch_bounds__(256, 2) ff_fused(
    const __half* __restrict__ hn, const __half* __restrict__ Bt1,
    const __half* __restrict__ Bt2,
    const float* __restrict__ b1, const float* __restrict__ slope,
    const float* __restrict__ b2, const float* __restrict__ hres,
    float* __restrict__ Cout, __half* __restrict__ xr)
{
    extern __shared__ char smem_raw[];
    const int tid  = threadIdx.x;
    const int lane = tid & 31;
    const int wid  = tid >> 5;
    const int warpm = wid & 1;
    const int warpn = wid >> 1;
    const int rowBase = blockIdx.x * 64;

    const uint32_t hnS = smem_u32(smem_raw);
    const uint32_t tS  = hnS + FF_A;
    const uint32_t bS  = tS + FF_A;
    __half* tHalf = (__half*)(smem_raw + FF_A);

    const uint32_t aLane =
        (uint32_t)(((warpm * 32) + (((lane >> 3) & 1) * 8) + (lane & 7)) * FPH
                   + (lane >> 4) * 8) * 2;
    const uint32_t bLane =
        (uint32_t)(((warpn * 32) + (((lane >> 4) & 1) * 8) + (lane & 7)) * HP
                   + ((lane >> 3) & 1) * 8) * 2;

    #pragma unroll
    for (int i = 0; i < 4; i++) {
        int chunk = tid + i * 256;
        int m = chunk >> 4;
        int q = (chunk & 15) * 8;
        int gr = rowBase + m;
        cp_async16(hnS + (uint32_t)(m * FPH + q) * 2,
                   hn + (size_t)(gr < NNODES ? gr : 0) * DM + q,
                   (gr < NNODES) ? 16u : 0u);
    }
    asm volatile("cp.async.commit_group;" ::: "memory");

    float accO[2][4][4];
    #pragma unroll
    for (int ms = 0; ms < 2; ms++)
        #pragma unroll
        for (int ns = 0; ns < 4; ns++)
            #pragma unroll
            for (int q = 0; q < 4; q++) accO[ms][ns][q] = 0.0f;

    const float slp = __ldg(slope);

    // acc += A(smem halves, pitch FPH) @ B(global half K-major, rowstride bstr)
    auto run_gemm = [&](uint32_t aSm, const __half* Bbase, int bstr,
                        float (*acc)[4][4]) {
        // one K32 B stage: 128 rows x 32 halves
        auto loadB = [&](int buf, int kt) {
            #pragma unroll
            for (int i = 0; i < 2; i++) {
                int c = tid + i * 256;
                int row = c >> 2;
                int kq  = (c & 3) * 8;
                cp_async16(bS + (uint32_t)(row * HP + kq) * 2 + buf * HSTAGEB,
                           Bbase + (size_t)row * bstr + kt * 32 + kq, 16u);
            }
            asm volatile("cp.async.commit_group;" ::: "memory");
        };
        __syncthreads();   // all warps done with prior reads of stage buffers
        loadB(0, 0);
        loadB(1, 1);
        #pragma unroll
        for (int kt = 0; kt < 4; kt++) {
            if (kt + 1 < 4) asm volatile("cp.async.wait_group 1;" ::: "memory");
            else            asm volatile("cp.async.wait_group 0;" ::: "memory");
            __syncthreads();
            if (kt + 2 < 4) loadB((kt + 2) % NSTAGE, kt + 2);

            const uint32_t sOff = (uint32_t)((kt % NSTAGE) * HSTAGEB);
            #pragma unroll
            for (int sub = 0; sub < 2; sub++) {
                uint32_t a[2][4], b[4][2];
                const uint32_t ak = aSm + aLane + (uint32_t)(kt * 32 + sub * 16) * 2;
                ldsm4(ak, a[0][0], a[0][1], a[0][2], a[0][3]);
                ldsm4(ak + 16 * FPH * 2, a[1][0], a[1][1], a[1][2], a[1][3]);
                const uint32_t bk = bS + bLane + sOff + sub * 32;
                #pragma unroll
                for (int p = 0; p < 2; p++)
                    ldsm4(bk + (uint32_t)(p * 16 * HP * 2),
                          b[2 * p][0], b[2 * p][1], b[2 * p + 1][0], b[2 * p + 1][1]);
                #pragma unroll
                for (int ms = 0; ms < 2; ms++)
                    #pragma unroll
                    for (int ns = 0; ns < 4; ns++)
                        mma_f16(acc[ms][ns], a[ms], b[ns]);
            }
        }
    };

    #pragma unroll 1
    for (int c = 0; c < 4; c++) {
        float accT[2][4][4];
        #pragma unroll
        for (int ms = 0; ms < 2; ms++)
            #pragma unroll
            for (int ns = 0; ns < 4; ns++)
                #pragma unroll
                for (int q = 0; q < 4; q++) accT[ms][ns][q] = 0.0f;

        run_gemm(hnS, Bt1 + (size_t)(c * 128) * DM, DM, accT);

        __syncthreads();
        const float* b1c = b1 + c * 128;
        #pragma unroll
        for (int ms = 0; ms < 2; ms++) {
            #pragma unroll
            for (int half = 0; half < 2; half++) {
                int r = warpm * 32 + ms * 16 + half * 8 + (lane >> 2);
                #pragma unroll
                for (int ns = 0; ns < 4; ns++) {
                    int cl = warpn * 32 + ns * 8 + (lane & 3) * 2;
                    float v0 = accT[ms][ns][half * 2 + 0] + __ldg(b1c + cl);
                    float v1 = accT[ms][ns][half * 2 + 1] + __ldg(b1c + cl + 1);
                    v0 = (v0 >= 0.0f) ? v0 : slp * v0;
                    v1 = (v1 >= 0.0f) ? v1 : slp * v1;
                    *(__half2*)&tHalf[r * FPH + cl] = __floats2half2_rn(v0, v1);
                }
            }
        }
        __syncthreads();

        run_gemm(tS, Bt2 + (size_t)(c * 128), DFFH, accO);
    }

    #pragma unroll
    for (int ms = 0; ms < 2; ms++) {
        #pragma unroll
        for (int half = 0; half < 2; half++) {
            int r = rowBase + warpm * 32 + ms * 16 + half * 8 + (lane >> 2);
            if (r >= NNODES) continue;
            #pragma unroll
            for (int ns = 0; ns < 4; ns++) {
                int cl = warpn * 32 + ns * 8 + (lane & 3) * 2;
                float2 hv = *(const float2*)&hres[(size_t)r * DM + cl];
                float v0 = accO[ms][ns][half * 2 + 0] + __ldg(b2 + cl)     + hv.x;
                float v1 = accO[ms][ns][half * 2 + 1] + __ldg(b2 + cl + 1) + hv.y;
                *(float2*)&Cout[(size_t)r * DM + cl] = make_float2(v0, v1);
                *(__half2*)&xr[(size_t)r * DM + cl] = __floats2half2_rn(v0, v1);
            }
        }
    }
}

// ---------------- batched transpose + fp16 convert (z = layer) ---------------
__global__ void transpose_h(const float* __restrict__ in, __half* __restrict__ out,
                            int K, int N)
{
    __shared__ float tile[32][33];
    size_t mat = (size_t)blockIdx.z * K * N;
    int k0 = blockIdx.x * 32, n0 = blockIdx.y * 32;
    int tx = threadIdx.x, ty = threadIdx.y;
    #pragma unroll
    for (int i = 0; i < 4; i++)
        tile[ty + i * 8][tx] = in[mat + (size_t)(k0 + ty + i * 8) * N + n0 + tx];
    __syncthreads();
    #pragma unroll
    for (int i = 0; i < 4; i++)
        out[mat + (size_t)(n0 + ty + i * 8) * K + k0 + tx] =
            __float2half_rn(tile[tx][ty + i * 8]);
}

// ---------------- convert layer-0 input to fp16 ------------------------------
__global__ void conv_half(const float* __restrict__ in, __half* __restrict__ out, int n4)
{
    int i = blockIdx.x * blockDim.x + threadIdx.x;
    if (i >= n4) return;
    float4 v = ((const float4*)in)[i];
    ((__half2*)out)[i * 2]     = __floats2half2_rn(v.x, v.y);
    ((__half2*)out)[i * 2 + 1] = __floats2half2_rn(v.z, v.w);
}

// ---------------- CSR build (once per call) ----------------------------------
__global__ void csr_zero()
{
    int i = blockIdx.x * blockDim.x + threadIdx.x;
    if (i <= NNODES) g_cnt[i] = 0;
}
__global__ void csr_hist(const int* __restrict__ dst)
{
    int e = blockIdx.x * blockDim.x + threadIdx.x;
    if (e < NEDGES) atomicAdd(&g_cnt[dst[e] + 1], 1);
}
__global__ void __launch_bounds__(1024) csr_scan()
{
    __shared__ int warpsum[32];
    const int T = 1024, TOT = NNODES + 1;
    const int ITEMS = (TOT + T - 1) / T;
    int t = threadIdx.x, lane = t & 31, w = t >> 5;
    int base = t * ITEMS;
    int sum = 0;
    for (int i = 0; i < ITEMS; i++) {
        int idx = base + i;
        if (idx < TOT) sum += g_cnt[idx];
    }
    int v = sum;
    #pragma unroll
    for (int o = 1; o < 32; o <<= 1) {
        int u = __shfl_up_sync(0xFFFFFFFFu, v, o);
        if (lane >= o) v += u;
    }
    if (lane == 31) warpsum[w] = v;
    __syncthreads();
    if (w == 0) {
        int wv = warpsum[lane];
        #pragma unroll
        for (int o = 1; o < 32; o <<= 1) {
            int u = __shfl_up_sync(0xFFFFFFFFu, wv, o);
            if (lane >= o) wv += u;
        }
        warpsum[lane] = wv;
    }
    __syncthreads();
    int excl = v - sum + (w > 0 ? warpsum[w - 1] : 0);
    int run = excl;
    for (int i = 0; i < ITEMS; i++) {
        int idx = base + i;
        if (idx < TOT) {
            run += g_cnt[idx];
            g_cnt[idx] = run;
            if (idx < NNODES) g_wo[idx] = run;
        }
    }
}
__global__ void csr_scatter(const int* __restrict__ src, const int* __restrict__ dst)
{
    int e = blockIdx.x * blockDim.x + threadIdx.x;
    if (e >= NEDGES) return;
    int d = dst[e];
    int pos = atomicAdd(&g_wo[d], 1);
    g_adj[pos] = src[e];
}

// ---------------- warp-per-node: softmax-agg + PReLU + 2x LayerNorm ----------
__global__ void __launch_bounds__(256) gat_agg_ln(
    const float* __restrict__ conv_bias, const float* __restrict__ a_conv,
    const float* __restrict__ ln_scale,  const float* __restrict__ ln_bias)
{
    int n = blockIdx.x * 8 + (threadIdx.x >> 5);
    if (n >= NNODES) return;
    int lane = threadIdx.x & 31;
    int h = lane >> 2;

    float myer = (lane < HH) ? g_er[n * HH + lane] : 0.0f;
    int beg = g_cnt[n], end = g_cnt[n + 1];

    float acc[4] = {0.f, 0.f, 0.f, 0.f};
    float den = 0.f;
    int i = beg;
    #pragma unroll 1
    for (; i + 4 <= end; i += 4) {
        int s0 = g_adj[i],     s1 = g_adj[i + 1];
        int s2 = g_adj[i + 2], s3 = g_adj[i + 3];
        float ex0 = 0.f, ex1 = 0.f, ex2 = 0.f, ex3 = 0.f;
        if (lane < HH) {
            float l0 = g_el[s0 * HH + lane] + myer;
            float l1 = g_el[s1 * HH + lane] + myer;
            float l2 = g_el[s2 * HH + lane] + myer;
            float l3 = g_el[s3 * HH + lane] + myer;
            l0 = (l0 >= 0.0f) ? l0 : 0.2f * l0;
            l1 = (l1 >= 0.0f) ? l1 : 0.2f * l1;
            l2 = (l2 >= 0.0f) ? l2 : 0.2f * l2;
            l3 = (l3 >= 0.0f) ? l3 : 0.2f * l3;
            ex0 = __expf(l0); ex1 = __expf(l1);
            ex2 = __expf(l2); ex3 = __expf(l3);
            den += (ex0 + ex1) + (ex2 + ex3);
        }
        float eb0 = __shfl_sync(0xFFFFFFFFu, ex0, h);
        float eb1 = __shfl_sync(0xFFFFFFFFu, ex1, h);
        float eb2 = __shfl_sync(0xFFFFFFFFu, ex2, h);
        float eb3 = __shfl_sync(0xFFFFFFFFu, ex3, h);
        float4 z0 = *(const float4*)&g_z[(size_t)s0 * DM + lane * 4];
        float4 z1 = *(const float4*)&g_z[(size_t)s1 * DM + lane * 4];
        float4 z2 = *(const float4*)&g_z[(size_t)s2 * DM + lane * 4];
        float4 z3 = *(const float4*)&g_z[(size_t)s3 * DM + lane * 4];
        acc[0] = fmaf(eb0, z0.x, acc[0]); acc[1] = fmaf(eb0, z0.y, acc[1]);
        acc[2] = fmaf(eb0, z0.z, acc[2]); acc[3] = fmaf(eb0, z0.w, acc[3]);
        acc[0] = fmaf(eb1, z1.x, acc[0]); acc[1] = fmaf(eb1, z1.y, acc[1]);
        acc[2] = fmaf(eb1, z1.z, acc[2]); acc[3] = fmaf(eb1, z1.w, acc[3]);
        acc[0] = fmaf(eb2, z2.x, acc[0]); acc[1] = fmaf(eb2, z2.y, acc[1]);
        acc[2] = fmaf(eb2, z2.z, acc[2]); acc[3] = fmaf(eb2, z2.w, acc[3]);
        acc[0] = fmaf(eb3, z3.x, acc[0]); acc[1] = fmaf(eb3, z3.y, acc[1]);
        acc[2] = fmaf(eb3, z3.z, acc[2]); acc[3] = fmaf(eb3, z3.w, acc[3]);
    }
    #pragma unroll 1
    for (; i < end; i++) {
        int s = g_adj[i];
        float ex = 0.f;
        if (lane < HH) {
            float lg = g_el[s * HH + lane] + myer;
            lg = (lg >= 0.0f) ? lg : 0.2f * lg;
            ex = __expf(lg);
            den += ex;
        }
        float exb = __shfl_sync(0xFFFFFFFFu, ex, h);
        float4 zv = *(const float4*)&g_z[(size_t)s * DM + lane * 4];
        acc[0] = fmaf(exb, zv.x, acc[0]);
        acc[1] = fmaf(exb, zv.y, acc[1]);
        acc[2] = fmaf(exb, zv.z, acc[2]);
        acc[3] = fmaf(exb, zv.w, acc[3]);
    }
    float denb = fmaxf(__shfl_sync(0xFFFFFFFFu, den, h), 1e-9f);

    int c = lane * 4;
    float4 cb = *(const float4*)&conv_bias[c];
    float a = __ldg(a_conv);
    float v[4] = {acc[0] / denb + cb.x, acc[1] / denb + cb.y,
                  acc[2] / denb + cb.z, acc[3] / denb + cb.w};
    #pragma unroll
    for (int q = 0; q < 4; q++) v[q] = (v[q] >= 0.0f) ? v[q] : a * v[q];

    float s = 0.f, s2 = 0.f;
    #pragma unroll
    for (int q = 0; q < 4; q++) { s += v[q]; s2 += v[q] * v[q]; }
    #pragma unroll
    for (int o = 16; o > 0; o >>= 1) {
        s  += __shfl_xor_sync(0xFFFFFFFFu, s, o);
        s2 += __shfl_xor_sync(0xFFFFFFFFu, s2, o);
    }
    float m = s * (1.0f / DM);
    float var = s2 * (1.0f / DM) - m * m;
    float inv = rsqrtf(var + 1e-5f);
    float4 lsc = *(const float4*)&ln_scale[c];
    float4 lbi = *(const float4*)&ln_bias[c];
    float hv[4];
    hv[0] = (v[0] - m) * inv * lsc.x + lbi.x;
    hv[1] = (v[1] - m) * inv * lsc.y + lbi.y;
    hv[2] = (v[2] - m) * inv * lsc.z + lbi.z;
    hv[3] = (v[3] - m) * inv * lsc.w + lbi.w;
    *(float4*)&g_h[(size_t)n * DM + c] = make_float4(hv[0], hv[1], hv[2], hv[3]);

    float t = 0.f, t2 = 0.f;
    #pragma unroll
    for (int q = 0; q < 4; q++) { t += hv[q]; t2 += hv[q] * hv[q]; }
    #pragma unroll
    for (int o = 16; o > 0; o >>= 1) {
        t  += __shfl_xor_sync(0xFFFFFFFFu, t, o);
        t2 += __shfl_xor_sync(0xFFFFFFFFu, t2, o);
    }
    float m2 = t * (1.0f / DM);
    float var2 = t2 * (1.0f / DM) - m2 * m2;
    float inv2 = rsqrtf(var2 + 1e-5f);
    float o0 = (hv[0] - m2) * inv2 * lsc.x + lbi.x;
    float o1 = (hv[1] - m2) * inv2 * lsc.y + lbi.y;
    float o2 = (hv[2] - m2) * inv2 * lsc.z + lbi.z;
    float o3 = (hv[3] - m2) * inv2 * lsc.w + lbi.w;
    *(__half2*)&g_hn[(size_t)n * DM + c]     = __floats2half2_rn(o0, o1);
    *(__half2*)&g_hn[(size_t)n * DM + c + 2] = __floats2half2_rn(o2, o3);
}

// ---------------- launcher ---------------------------------------------------
extern "C" void kernel_launch(void* const* d_in, const int* in_sizes, int n_in,
                              void* d_out, int out_size)
{
    const float* in_feats = (const float*)d_in[0];
    const int*   src      = (const int*)  d_in[1];
    const int*   dst      = (const int*)  d_in[2];
    const float* W        = (const float*)d_in[3];
    const float* attn_l   = (const float*)d_in[4];
    const float* attn_r   = (const float*)d_in[5];
    const float* conv_b   = (const float*)d_in[6];
    const float* a_conv   = (const float*)d_in[7];
    const float* ln_scale = (const float*)d_in[8];
    const float* ln_bias  = (const float*)d_in[9];
    const float* W1       = (const float*)d_in[10];
    const float* b1       = (const float*)d_in[11];
    const float* W2       = (const float*)d_in[12];
    const float* b2       = (const float*)d_in[13];
    const float* a_ff     = (const float*)d_in[14];
    float* out = (float*)d_out;

    float *zP, *hP;
    __half *xrP, *hnP, *btP;
    cudaGetSymbolAddress((void**)&zP,  g_z);
    cudaGetSymbolAddress((void**)&xrP, g_xr);
    cudaGetSymbolAddress((void**)&hP,  g_h);
    cudaGetSymbolAddress((void**)&hnP, g_hn);
    cudaGetSymbolAddress((void**)&btP, g_bt);

    cudaFuncSetAttribute(gemm_z, cudaFuncAttributeMaxDynamicSharedMemorySize, G0SMEM);
    cudaFuncSetAttribute(ff_fused, cudaFuncAttributeMaxDynamicSharedMemorySize, FF_SMEM);

    const int E_BLOCKS = (NEDGES + 255) / 256;
    const int RC_BLOCKS = (NNODES * DM / 4 + 255) / 256;

    // batched weight transposes -> fp16 (z = layer)
    transpose_h<<<dim3(DM / 32, DM / 32, 3), dim3(32, 8)>>>(W, btP + OFF_W(0), DM, DM);
    transpose_h<<<dim3(DM / 32, DFFH / 32, 3), dim3(32, 8)>>>(W1, btP + OFF_W1(0), DM, DFFH);
    transpose_h<<<dim3(DFFH / 32, DM / 32, 3), dim3(32, 8)>>>(W2, btP + OFF_W2(0), DFFH, DM);
    conv_half<<<RC_BLOCKS, 256>>>(in_feats, xrP, NNODES * DM / 4);

    // CSR build (graph fixed across layers)
    csr_zero<<<(NNODES + 256) / 256, 256>>>();
    csr_hist<<<E_BLOCKS, 256>>>(dst);
    csr_scan<<<1, 1024>>>();
    csr_scatter<<<E_BLOCKS, 256>>>(src, dst);

    for (int l = 0; l < LL; l++) {
        // z = xr @ W  (+ fused el/er)
        gemm_z<<<dim3(1, MTILES), 256, G0SMEM>>>(
            xrP, btP + OFF_W(l), zP,
            attn_l + (size_t)l * DM, attn_r + (size_t)l * DM);

        gat_agg_ln<<<(NNODES + 7) / 8, 256>>>(conv_b + (size_t)l * DM, a_conv + l,
                                              ln_scale + (size_t)l * DM,
                                              ln_bias + (size_t)l * DM);

        // out[l] = h + prelu(hn@W1+b1)@W2 + b2 ; xr = fp16(out[l])
        ff_fused<<<FTILES, 256, FF_SMEM>>>(
            hnP, btP + OFF_W1(l), btP + OFF_W2(l),
            b1 + (size_t)l * DFFH, a_ff + l, b2 + (size_t)l * DM,
            hP, out + (size_t)l * NNODES * DM, xrP);
    }
}

// round 15
// speedup vs baseline: 1.6534x; 1.1903x over previous
#include <cuda_runtime.h>
#include <cuda_fp16.h>
#include <math.h>
#include <stdint.h>

#define NNODES 50000
#define NEDGES 600000
#define DM 128
#define HH 8
#define DH 16
#define DFFH 512
#define LL 3
#define MTILES ((NNODES + 127) / 128)   // 391
#define FTILES ((NNODES + 63) / 64)     // 782
#define SCAN_B ((NNODES + 1 + 511) / 512)   // 98

// ---------------- scratch (static device memory; no allocs allowed) --------
__device__ float  g_z [(size_t)NNODES * DM];     // fp32 projected features
__device__ __half g_xr[(size_t)NNODES * DM];     // fp16 layer input
__device__ float  g_el[(size_t)NNODES * HH];
__device__ float  g_er[(size_t)NNODES * HH];
__device__ float  g_h [(size_t)NNODES * DM];
__device__ __half g_hn[(size_t)NNODES * DM];     // fp16
__device__ __half g_bt[(size_t)3 * (DM * DM + DM * DFFH + DFFH * DM)]; // all W^T fp16
__device__ int    g_cnt[NNODES + 1];             // counts -> rowptr
__device__ int    g_wo [NNODES];                 // scatter write offsets
__device__ int    g_adj[NEDGES];                 // src ids grouped by dst
__device__ int    g_bsum[SCAN_B];                // scan block sums

#define OFF_W(l)  ((size_t)(l) * DM * DM)
#define OFF_W1(l) ((size_t)3 * DM * DM + (size_t)(l) * DM * DFFH)
#define OFF_W2(l) ((size_t)3 * DM * DM + (size_t)3 * DM * DFFH + (size_t)(l) * DFFH * DM)

// ---------------- helpers ------------------------------------------------
__device__ __forceinline__ uint32_t smem_u32(const void* p) {
    uint32_t a;
    asm("{ .reg .u64 t; cvta.to.shared.u64 t, %1; cvt.u32.u64 %0, t; }" : "=r"(a) : "l"(p));
    return a;
}
__device__ __forceinline__ void cp_async16(uint32_t saddr, const void* gaddr, uint32_t sz) {
    asm volatile("cp.async.cg.shared.global [%0], [%1], 16, %2;"
                 :: "r"(saddr), "l"(gaddr), "r"(sz) : "memory");
}
// fp16 mma: D(f32) += A(f16, m16k16) * B(f16, k16n8)
__device__ __forceinline__ void mma_f16(float* c, const uint32_t* a, const uint32_t* b) {
    asm volatile("mma.sync.aligned.m16n8k16.row.col.f32.f16.f16.f32 "
                 "{%0,%1,%2,%3}, {%4,%5,%6,%7}, {%8,%9}, {%0,%1,%2,%3};"
                 : "+f"(c[0]), "+f"(c[1]), "+f"(c[2]), "+f"(c[3])
                 : "r"(a[0]), "r"(a[1]), "r"(a[2]), "r"(a[3]),
                   "r"(b[0]), "r"(b[1]));
}
__device__ __forceinline__ void ldsm4(uint32_t addr, uint32_t& r0, uint32_t& r1,
                                      uint32_t& r2, uint32_t& r3) {
    asm volatile("ldmatrix.sync.aligned.m8n8.x4.shared.b16 {%0,%1,%2,%3}, [%4];"
                 : "=r"(r0), "=r"(r1), "=r"(r2), "=r"(r3) : "r"(addr));
}

#define HP 40                              // halves per staged row (32 + 8 pad)
#define HSTAGEB (128 * HP * 2)             // 10240 bytes per matrix per k32 stage
#define NSTAGE 3
#define G0SMEM (2 * NSTAGE * HSTAGEB)      // 61440 bytes

// ---------------- fp16 mma GEMM: z-projection + fused el/er ------------------
__global__ void __launch_bounds__(256, 2) gemm_z(
    const __half* __restrict__ A, const __half* __restrict__ Bt,
    float* __restrict__ C,
    const float* __restrict__ attn_l, const float* __restrict__ attn_r)
{
    extern __shared__ char smem_raw[];
    __shared__ float sAL[DM], sAR[DM];

    const int tid  = threadIdx.x;
    const int lane = tid & 31;
    const int wid  = tid >> 5;
    const int warpm = wid & 3;          // 4 warps along M (32 rows)
    const int warpn = wid >> 2;         // 2 warps along N (64 cols)
    const int rowBase = blockIdx.y * 128;

    if (tid < DM) { sAL[tid] = attn_l[tid]; sAR[tid] = attn_r[tid]; }
    __syncthreads();

    const uint32_t aS = smem_u32(smem_raw);
    const uint32_t bS = aS + NSTAGE * HSTAGEB;

    const uint32_t aBase = aS +
        (uint32_t)(((warpm * 32) + (((lane >> 3) & 1) * 8) + (lane & 7)) * HP
                   + (lane >> 4) * 8) * 2;
    const uint32_t bBase = bS +
        (uint32_t)(((warpn * 64) + (((lane >> 4) & 1) * 8) + (lane & 7)) * HP
                   + ((lane >> 3) & 1) * 8) * 2;

    auto load_stage = [&](int buf, int k0) {
        #pragma unroll
        for (int i = 0; i < 2; i++) {
            int c = tid + i * 256;
            int row = c >> 2;
            int kq  = (c & 3) * 8;
            uint32_t soff = (uint32_t)(row * HP + kq) * 2 + buf * HSTAGEB;
            int gr = rowBase + row;
            cp_async16(aS + soff,
                       A + (size_t)(gr < NNODES ? gr : 0) * DM + k0 + kq,
                       (gr < NNODES) ? 16u : 0u);
            cp_async16(bS + soff,
                       Bt + (size_t)row * DM + k0 + kq, 16u);
        }
        asm volatile("cp.async.commit_group;" ::: "memory");
    };

    float acc[2][8][4];
    #pragma unroll
    for (int ms = 0; ms < 2; ms++)
        #pragma unroll
        for (int ns = 0; ns < 8; ns++)
            #pragma unroll
            for (int q = 0; q < 4; q++) acc[ms][ns][q] = 0.0f;

    load_stage(0, 0);
    load_stage(1, 32);

    #pragma unroll
    for (int kt = 0; kt < 4; ++kt) {
        if (kt + 1 < 4) asm volatile("cp.async.wait_group 1;" ::: "memory");
        else            asm volatile("cp.async.wait_group 0;" ::: "memory");
        __syncthreads();
        if (kt + 2 < 4) load_stage((kt + 2) % NSTAGE, (kt + 2) * 32);

        const uint32_t sOff = (uint32_t)((kt % NSTAGE) * HSTAGEB);
        #pragma unroll
        for (int sub = 0; sub < 2; sub++) {
            const uint32_t kOff = sOff + sub * 32;
            uint32_t a[2][4], b[8][2];
            ldsm4(aBase + kOff, a[0][0], a[0][1], a[0][2], a[0][3]);
            ldsm4(aBase + kOff + 16 * HP * 2, a[1][0], a[1][1], a[1][2], a[1][3]);
            #pragma unroll
            for (int p = 0; p < 4; p++)
                ldsm4(bBase + kOff + (uint32_t)(p * 16 * HP * 2),
                      b[2 * p][0], b[2 * p][1], b[2 * p + 1][0], b[2 * p + 1][1]);
            #pragma unroll
            for (int ms = 0; ms < 2; ms++)
                #pragma unroll
                for (int ns = 0; ns < 8; ns++)
                    mma_f16(acc[ms][ns], a[ms], b[ns]);
        }
    }

    // epilogue: store z (fp32) + fused el/er
    #pragma unroll
    for (int ms = 0; ms < 2; ms++) {
        #pragma unroll
        for (int half = 0; half < 2; half++) {
            int r = rowBase + warpm * 32 + ms * 16 + half * 8 + (lane >> 2);
            const bool valid = (r < NNODES);
            float psl[4], psr[4];
            #pragma unroll
            for (int q = 0; q < 4; q++) { psl[q] = 0.f; psr[q] = 0.f; }
            #pragma unroll
            for (int ns = 0; ns < 8; ns++) {
                int cl = warpn * 64 + ns * 8 + (lane & 3) * 2;
                float v0 = acc[ms][ns][half * 2 + 0];
                float v1 = acc[ms][ns][half * 2 + 1];
                if (valid)
                    *(float2*)&C[(size_t)r * DM + cl] = make_float2(v0, v1);
                int hh = ns >> 1;
                psl[hh] += v0 * sAL[cl] + v1 * sAL[cl + 1];
                psr[hh] += v0 * sAR[cl] + v1 * sAR[cl + 1];
            }
            #pragma unroll
            for (int d = 1; d <= 2; d <<= 1) {
                #pragma unroll
                for (int q = 0; q < 4; q++) {
                    psl[q] += __shfl_xor_sync(0xFFFFFFFFu, psl[q], d);
                    psr[q] += __shfl_xor_sync(0xFFFFFFFFu, psr[q], d);
                }
            }
            if ((lane & 3) == 0 && valid) {
                #pragma unroll
                for (int q = 0; q < 4; q++) {
                    int hidx = r * HH + warpn * 4 + q;
                    g_el[hidx] = psl[q];
                    g_er[hidx] = psr[q];
                }
            }
        }
    }
}

// ---------------- fused FeedForward (fp16): 64-row blocks --------------------
#define FPH 136
#define FF_A (64 * FPH * 2)
#define FF_SMEM (2 * FF_A + NSTAGE * HSTAGEB)    // 65536

__global__ void __launch_bounds__(256, 2) ff_fused(
    const __half* __restrict__ hn, const __half* __restrict__ Bt1,
    const __half* __restrict__ Bt2,
    const float* __restrict__ b1, const float* __restrict__ slope,
    const float* __restrict__ b2, const float* __restrict__ hres,
    float* __restrict__ Cout, __half* __restrict__ xr)
{
    extern __shared__ char smem_raw[];
    const int tid  = threadIdx.x;
    const int lane = tid & 31;
    const int wid  = tid >> 5;
    const int warpm = wid & 1;
    const int warpn = wid >> 1;
    const int rowBase = blockIdx.x * 64;

    const uint32_t hnS = smem_u32(smem_raw);
    const uint32_t tS  = hnS + FF_A;
    const uint32_t bS  = tS + FF_A;
    __half* tHalf = (__half*)(smem_raw + FF_A);

    const uint32_t aLane =
        (uint32_t)(((warpm * 32) + (((lane >> 3) & 1) * 8) + (lane & 7)) * FPH
                   + (lane >> 4) * 8) * 2;
    const uint32_t bLane =
        (uint32_t)(((warpn * 32) + (((lane >> 4) & 1) * 8) + (lane & 7)) * HP
                   + ((lane >> 3) & 1) * 8) * 2;

    #pragma unroll
    for (int i = 0; i < 4; i++) {
        int chunk = tid + i * 256;
        int m = chunk >> 4;
        int q = (chunk & 15) * 8;
        int gr = rowBase + m;
        cp_async16(hnS + (uint32_t)(m * FPH + q) * 2,
                   hn + (size_t)(gr < NNODES ? gr : 0) * DM + q,
                   (gr < NNODES) ? 16u : 0u);
    }
    asm volatile("cp.async.commit_group;" ::: "memory");

    float accO[2][4][4];
    #pragma unroll
    for (int ms = 0; ms < 2; ms++)
        #pragma unroll
        for (int ns = 0; ns < 4; ns++)
            #pragma unroll
            for (int q = 0; q < 4; q++) accO[ms][ns][q] = 0.0f;

    const float slp = __ldg(slope);

    auto run_gemm = [&](uint32_t aSm, const __half* Bbase, int bstr,
                        float (*acc)[4][4]) {
        auto loadB = [&](int buf, int kt) {
            #pragma unroll
            for (int i = 0; i < 2; i++) {
                int c = tid + i * 256;
                int row = c >> 2;
                int kq  = (c & 3) * 8;
                cp_async16(bS + (uint32_t)(row * HP + kq) * 2 + buf * HSTAGEB,
                           Bbase + (size_t)row * bstr + kt * 32 + kq, 16u);
            }
            asm volatile("cp.async.commit_group;" ::: "memory");
        };
        __syncthreads();
        loadB(0, 0);
        loadB(1, 1);
        #pragma unroll
        for (int kt = 0; kt < 4; kt++) {
            if (kt + 1 < 4) asm volatile("cp.async.wait_group 1;" ::: "memory");
            else            asm volatile("cp.async.wait_group 0;" ::: "memory");
            __syncthreads();
            if (kt + 2 < 4) loadB((kt + 2) % NSTAGE, kt + 2);

            const uint32_t sOff = (uint32_t)((kt % NSTAGE) * HSTAGEB);
            #pragma unroll
            for (int sub = 0; sub < 2; sub++) {
                uint32_t a[2][4], b[4][2];
                const uint32_t ak = aSm + aLane + (uint32_t)(kt * 32 + sub * 16) * 2;
                ldsm4(ak, a[0][0], a[0][1], a[0][2], a[0][3]);
                ldsm4(ak + 16 * FPH * 2, a[1][0], a[1][1], a[1][2], a[1][3]);
                const uint32_t bk = bS + bLane + sOff + sub * 32;
                #pragma unroll
                for (int p = 0; p < 2; p++)
                    ldsm4(bk + (uint32_t)(p * 16 * HP * 2),
                          b[2 * p][0], b[2 * p][1], b[2 * p + 1][0], b[2 * p + 1][1]);
                #pragma unroll
                for (int ms = 0; ms < 2; ms++)
                    #pragma unroll
                    for (int ns = 0; ns < 4; ns++)
                        mma_f16(acc[ms][ns], a[ms], b[ns]);
            }
        }
    };

    #pragma unroll 1
    for (int c = 0; c < 4; c++) {
        float accT[2][4][4];
        #pragma unroll
        for (int ms = 0; ms < 2; ms++)
            #pragma unroll
            for (int ns = 0; ns < 4; ns++)
                #pragma unroll
                for (int q = 0; q < 4; q++) accT[ms][ns][q] = 0.0f;

        run_gemm(hnS, Bt1 + (size_t)(c * 128) * DM, DM, accT);

        __syncthreads();
        const float* b1c = b1 + c * 128;
        #pragma unroll
        for (int ms = 0; ms < 2; ms++) {
            #pragma unroll
            for (int half = 0; half < 2; half++) {
                int r = warpm * 32 + ms * 16 + half * 8 + (lane >> 2);
                #pragma unroll
                for (int ns = 0; ns < 4; ns++) {
                    int cl = warpn * 32 + ns * 8 + (lane & 3) * 2;
                    float v0 = accT[ms][ns][half * 2 + 0] + __ldg(b1c + cl);
                    float v1 = accT[ms][ns][half * 2 + 1] + __ldg(b1c + cl + 1);
                    v0 = (v0 >= 0.0f) ? v0 : slp * v0;
                    v1 = (v1 >= 0.0f) ? v1 : slp * v1;
                    *(__half2*)&tHalf[r * FPH + cl] = __floats2half2_rn(v0, v1);
                }
            }
        }
        __syncthreads();

        run_gemm(tS, Bt2 + (size_t)(c * 128), DFFH, accO);
    }

    #pragma unroll
    for (int ms = 0; ms < 2; ms++) {
        #pragma unroll
        for (int half = 0; half < 2; half++) {
            int r = rowBase + warpm * 32 + ms * 16 + half * 8 + (lane >> 2);
            if (r >= NNODES) continue;
            #pragma unroll
            for (int ns = 0; ns < 4; ns++) {
                int cl = warpn * 32 + ns * 8 + (lane & 3) * 2;
                float2 hv = *(const float2*)&hres[(size_t)r * DM + cl];
                float v0 = accO[ms][ns][half * 2 + 0] + __ldg(b2 + cl)     + hv.x;
                float v1 = accO[ms][ns][half * 2 + 1] + __ldg(b2 + cl + 1) + hv.y;
                *(float2*)&Cout[(size_t)r * DM + cl] = make_float2(v0, v1);
                *(__half2*)&xr[(size_t)r * DM + cl] = __floats2half2_rn(v0, v1);
            }
        }
    }
}

// ---------------- batched transpose + fp16 convert (z = layer) ---------------
__global__ void transpose_h(const float* __restrict__ in, __half* __restrict__ out,
                            int K, int N)
{
    __shared__ float tile[32][33];
    size_t mat = (size_t)blockIdx.z * K * N;
    int k0 = blockIdx.x * 32, n0 = blockIdx.y * 32;
    int tx = threadIdx.x, ty = threadIdx.y;
    #pragma unroll
    for (int i = 0; i < 4; i++)
        tile[ty + i * 8][tx] = in[mat + (size_t)(k0 + ty + i * 8) * N + n0 + tx];
    __syncthreads();
    #pragma unroll
    for (int i = 0; i < 4; i++)
        out[mat + (size_t)(n0 + ty + i * 8) * K + k0 + tx] =
            __float2half_rn(tile[tx][ty + i * 8]);
}

// ---------------- convert layer-0 input to fp16 ------------------------------
__global__ void conv_half(const float* __restrict__ in, __half* __restrict__ out, int n4)
{
    int i = blockIdx.x * blockDim.x + threadIdx.x;
    if (i >= n4) return;
    float4 v = ((const float4*)in)[i];
    ((__half2*)out)[i * 2]     = __floats2half2_rn(v.x, v.y);
    ((__half2*)out)[i * 2 + 1] = __floats2half2_rn(v.z, v.w);
}

// ---------------- CSR build (once per call) ----------------------------------
__global__ void csr_zero()
{
    int i = blockIdx.x * blockDim.x + threadIdx.x;
    if (i <= NNODES) g_cnt[i] = 0;
}
__global__ void csr_hist(const int* __restrict__ dst)
{
    int e = blockIdx.x * blockDim.x + threadIdx.x;
    if (e < NEDGES) atomicAdd(&g_cnt[dst[e] + 1], 1);
}
// hierarchical scan: phase 1 — per-block (512) inclusive scan + block sums
__global__ void __launch_bounds__(512) csr_scan1()
{
    __shared__ int ws[16];
    int t = threadIdx.x;
    int lane = t & 31, w = t >> 5;
    int idx = blockIdx.x * 512 + t;
    int v = (idx <= NNODES) ? g_cnt[idx] : 0;
    int x = v;
    #pragma unroll
    for (int o = 1; o < 32; o <<= 1) {
        int u = __shfl_up_sync(0xFFFFFFFFu, x, o);
        if (lane >= o) x += u;
    }
    if (lane == 31) ws[w] = x;
    __syncthreads();
    if (w == 0) {
        int y = (lane < 16) ? ws[lane] : 0;
        #pragma unroll
        for (int o = 1; o < 16; o <<= 1) {
            int u = __shfl_up_sync(0xFFFFFFFFu, y, o);
            if (lane >= o) y += u;
        }
        if (lane < 16) ws[lane] = y;
    }
    __syncthreads();
    int incl = x + (w > 0 ? ws[w - 1] : 0);
    if (idx <= NNODES) g_cnt[idx] = incl;
    if (t == 511) g_bsum[blockIdx.x] = incl;
}
// phase 2 — scan block sums (SCAN_B <= 128) into exclusive prefixes
__global__ void __launch_bounds__(128) csr_scan2()
{
    __shared__ int ws[4];
    int t = threadIdx.x;
    int lane = t & 31, w = t >> 5;
    int v = (t < SCAN_B) ? g_bsum[t] : 0;
    int x = v;
    #pragma unroll
    for (int o = 1; o < 32; o <<= 1) {
        int u = __shfl_up_sync(0xFFFFFFFFu, x, o);
        if (lane >= o) x += u;
    }
    if (lane == 31) ws[w] = x;
    __syncthreads();
    int add = 0;
    if (w > 0) add = ws[0];
    if (w > 1) add += ws[1];
    if (w > 2) add += ws[2];
    if (t < SCAN_B) g_bsum[t] = x + add - v;   // exclusive prefix
}
// phase 3 — add block prefix; emit rowptr + write offsets
__global__ void __launch_bounds__(512) csr_scan3()
{
    int idx = blockIdx.x * 512 + threadIdx.x;
    if (idx <= NNODES) {
        int val = g_cnt[idx] + g_bsum[blockIdx.x];
        g_cnt[idx] = val;
        if (idx < NNODES) g_wo[idx] = val;
    }
}
__global__ void csr_scatter(const int* __restrict__ src, const int* __restrict__ dst)
{
    int e = blockIdx.x * blockDim.x + threadIdx.x;
    if (e >= NEDGES) return;
    int d = dst[e];
    int pos = atomicAdd(&g_wo[d], 1);
    g_adj[pos] = src[e];
}

// ---------------- warp-per-node: softmax-agg + PReLU + 2x LayerNorm ----------
__global__ void __launch_bounds__(256) gat_agg_ln(
    const float* __restrict__ conv_bias, const float* __restrict__ a_conv,
    const float* __restrict__ ln_scale,  const float* __restrict__ ln_bias)
{
    int n = blockIdx.x * 8 + (threadIdx.x >> 5);
    if (n >= NNODES) return;
    int lane = threadIdx.x & 31;
    int h = lane >> 2;

    float myer = (lane < HH) ? g_er[n * HH + lane] : 0.0f;
    int beg = g_cnt[n], end = g_cnt[n + 1];

    float acc[4] = {0.f, 0.f, 0.f, 0.f};
    float den = 0.f;
    int i = beg;
    #pragma unroll 1
    for (; i + 4 <= end; i += 4) {
        int s0 = g_adj[i],     s1 = g_adj[i + 1];
        int s2 = g_adj[i + 2], s3 = g_adj[i + 3];
        float ex0 = 0.f, ex1 = 0.f, ex2 = 0.f, ex3 = 0.f;
        if (lane < HH) {
            float l0 = g_el[s0 * HH + lane] + myer;
            float l1 = g_el[s1 * HH + lane] + myer;
            float l2 = g_el[s2 * HH + lane] + myer;
            float l3 = g_el[s3 * HH + lane] + myer;
            l0 = (l0 >= 0.0f) ? l0 : 0.2f * l0;
            l1 = (l1 >= 0.0f) ? l1 : 0.2f * l1;
            l2 = (l2 >= 0.0f) ? l2 : 0.2f * l2;
            l3 = (l3 >= 0.0f) ? l3 : 0.2f * l3;
            ex0 = __expf(l0); ex1 = __expf(l1);
            ex2 = __expf(l2); ex3 = __expf(l3);
            den += (ex0 + ex1) + (ex2 + ex3);
        }
        float eb0 = __shfl_sync(0xFFFFFFFFu, ex0, h);
        float eb1 = __shfl_sync(0xFFFFFFFFu, ex1, h);
        float eb2 = __shfl_sync(0xFFFFFFFFu, ex2, h);
        float eb3 = __shfl_sync(0xFFFFFFFFu, ex3, h);
        float4 z0 = *(const float4*)&g_z[(size_t)s0 * DM + lane * 4];
        float4 z1 = *(const float4*)&g_z[(size_t)s1 * DM + lane * 4];
        float4 z2 = *(const float4*)&g_z[(size_t)s2 * DM + lane * 4];
        float4 z3 = *(const float4*)&g_z[(size_t)s3 * DM + lane * 4];
        acc[0] = fmaf(eb0, z0.x, acc[0]); acc[1] = fmaf(eb0, z0.y, acc[1]);
        acc[2] = fmaf(eb0, z0.z, acc[2]); acc[3] = fmaf(eb0, z0.w, acc[3]);
        acc[0] = fmaf(eb1, z1.x, acc[0]); acc[1] = fmaf(eb1, z1.y, acc[1]);
        acc[2] = fmaf(eb1, z1.z, acc[2]); acc[3] = fmaf(eb1, z1.w, acc[3]);
        acc[0] = fmaf(eb2, z2.x, acc[0]); acc[1] = fmaf(eb2, z2.y, acc[1]);
        acc[2] = fmaf(eb2, z2.z, acc[2]); acc[3] = fmaf(eb2, z2.w, acc[3]);
        acc[0] = fmaf(eb3, z3.x, acc[0]); acc[1] = fmaf(eb3, z3.y, acc[1]);
        acc[2] = fmaf(eb3, z3.z, acc[2]); acc[3] = fmaf(eb3, z3.w, acc[3]);
    }
    #pragma unroll 1
    for (; i < end; i++) {
        int s = g_adj[i];
        float ex = 0.f;
        if (lane < HH) {
            float lg = g_el[s * HH + lane] + myer;
            lg = (lg >= 0.0f) ? lg : 0.2f * lg;
            ex = __expf(lg);
            den += ex;
        }
        float exb = __shfl_sync(0xFFFFFFFFu, ex, h);
        float4 zv = *(const float4*)&g_z[(size_t)s * DM + lane * 4];
        acc[0] = fmaf(exb, zv.x, acc[0]);
        acc[1] = fmaf(exb, zv.y, acc[1]);
        acc[2] = fmaf(exb, zv.z, acc[2]);
        acc[3] = fmaf(exb, zv.w, acc[3]);
    }
    float denb = fmaxf(__shfl_sync(0xFFFFFFFFu, den, h), 1e-9f);

    int c = lane * 4;
    float4 cb = *(const float4*)&conv_bias[c];
    float a = __ldg(a_conv);
    float v[4] = {acc[0] / denb + cb.x, acc[1] / denb + cb.y,
                  acc[2] / denb + cb.z, acc[3] / denb + cb.w};
    #pragma unroll
    for (int q = 0; q < 4; q++) v[q] = (v[q] >= 0.0f) ? v[q] : a * v[q];

    float s = 0.f, s2 = 0.f;
    #pragma unroll
    for (int q = 0; q < 4; q++) { s += v[q]; s2 += v[q] * v[q]; }
    #pragma unroll
    for (int o = 16; o > 0; o >>= 1) {
        s  += __shfl_xor_sync(0xFFFFFFFFu, s, o);
        s2 += __shfl_xor_sync(0xFFFFFFFFu, s2, o);
    }
    float m = s * (1.0f / DM);
    float var = s2 * (1.0f / DM) - m * m;
    float inv = rsqrtf(var + 1e-5f);
    float4 lsc = *(const float4*)&ln_scale[c];
    float4 lbi = *(const float4*)&ln_bias[c];
    float hv[4];
    hv[0] = (v[0] - m) * inv * lsc.x + lbi.x;
    hv[1] = (v[1] - m) * inv * lsc.y + lbi.y;
    hv[2] = (v[2] - m) * inv * lsc.z + lbi.z;
    hv[3] = (v[3] - m) * inv * lsc.w + lbi.w;
    *(float4*)&g_h[(size_t)n * DM + c] = make_float4(hv[0], hv[1], hv[2], hv[3]);

    float t = 0.f, t2 = 0.f;
    #pragma unroll
    for (int q = 0; q < 4; q++) { t += hv[q]; t2 += hv[q] * hv[q]; }
    #pragma unroll
    for (int o = 16; o > 0; o >>= 1) {
        t  += __shfl_xor_sync(0xFFFFFFFFu, t, o);
        t2 += __shfl_xor_sync(0xFFFFFFFFu, t2, o);
    }
    float m2 = t * (1.0f / DM);
    float var2 = t2 * (1.0f / DM) - m2 * m2;
    float inv2 = rsqrtf(var2 + 1e-5f);
    float o0 = (hv[0] - m2) * inv2 * lsc.x + lbi.x;
    float o1 = (hv[1] - m2) * inv2 * lsc.y + lbi.y;
    float o2 = (hv[2] - m2) * inv2 * lsc.z + lbi.z;
    float o3 = (hv[3] - m2) * inv2 * lsc.w + lbi.w;
    *(__half2*)&g_hn[(size_t)n * DM + c]     = __floats2half2_rn(o0, o1);
    *(__half2*)&g_hn[(size_t)n * DM + c + 2] = __floats2half2_rn(o2, o3);
}

// ---------------- launcher ---------------------------------------------------
extern "C" void kernel_launch(void* const* d_in, const int* in_sizes, int n_in,
                              void* d_out, int out_size)
{
    const float* in_feats = (const float*)d_in[0];
    const int*   src      = (const int*)  d_in[1];
    const int*   dst      = (const int*)  d_in[2];
    const float* W        = (const float*)d_in[3];
    const float* attn_l   = (const float*)d_in[4];
    const float* attn_r   = (const float*)d_in[5];
    const float* conv_b   = (const float*)d_in[6];
    const float* a_conv   = (const float*)d_in[7];
    const float* ln_scale = (const float*)d_in[8];
    const float* ln_bias  = (const float*)d_in[9];
    const float* W1       = (const float*)d_in[10];
    const float* b1       = (const float*)d_in[11];
    const float* W2       = (const float*)d_in[12];
    const float* b2       = (const float*)d_in[13];
    const float* a_ff     = (const float*)d_in[14];
    float* out = (float*)d_out;

    float *zP, *hP;
    __half *xrP, *hnP, *btP;
    cudaGetSymbolAddress((void**)&zP,  g_z);
    cudaGetSymbolAddress((void**)&xrP, g_xr);
    cudaGetSymbolAddress((void**)&hP,  g_h);
    cudaGetSymbolAddress((void**)&hnP, g_hn);
    cudaGetSymbolAddress((void**)&btP, g_bt);

    cudaFuncSetAttribute(gemm_z, cudaFuncAttributeMaxDynamicSharedMemorySize, G0SMEM);
    cudaFuncSetAttribute(ff_fused, cudaFuncAttributeMaxDynamicSharedMemorySize, FF_SMEM);

    // one-time infrastructure (streams/events; no device memory, identical
    // captured work on every call)
    static cudaStream_t sCsr = nullptr, sWt = nullptr;
    static cudaEvent_t evFork = nullptr, evCsr = nullptr, evWt = nullptr;
    if (sCsr == nullptr) {
        cudaStreamCreateWithFlags(&sCsr, cudaStreamNonBlocking);
        cudaStreamCreateWithFlags(&sWt, cudaStreamNonBlocking);
        cudaEventCreateWithFlags(&evFork, cudaEventDisableTiming);
        cudaEventCreateWithFlags(&evCsr, cudaEventDisableTiming);
        cudaEventCreateWithFlags(&evWt, cudaEventDisableTiming);
    }

    const int E_BLOCKS = (NEDGES + 255) / 256;
    const int RC_BLOCKS = (NNODES * DM / 4 + 255) / 256;

    // ---- fork side branches off the main (capture-origin) stream ----
    cudaEventRecord(evFork, 0);
    cudaStreamWaitEvent(sCsr, evFork, 0);
    cudaStreamWaitEvent(sWt, evFork, 0);

    // branch 1: CSR build (needed by first gat_agg_ln)
    csr_zero<<<(NNODES + 256) / 256, 256, 0, sCsr>>>();
    csr_hist<<<E_BLOCKS, 256, 0, sCsr>>>(dst);
    csr_scan1<<<SCAN_B, 512, 0, sCsr>>>();
    csr_scan2<<<1, 128, 0, sCsr>>>();
    csr_scan3<<<SCAN_B, 512, 0, sCsr>>>();
    csr_scatter<<<E_BLOCKS, 256, 0, sCsr>>>(src, dst);
    cudaEventRecord(evCsr, sCsr);

    // branch 2: W1/W2 transposes (needed by first ff_fused)
    transpose_h<<<dim3(DM / 32, DFFH / 32, 3), dim3(32, 8), 0, sWt>>>(
        W1, btP + OFF_W1(0), DM, DFFH);
    transpose_h<<<dim3(DFFH / 32, DM / 32, 3), dim3(32, 8), 0, sWt>>>(
        W2, btP + OFF_W2(0), DFFH, DM);
    cudaEventRecord(evWt, sWt);

    // main: W transpose + input convert (needed by first gemm_z)
    transpose_h<<<dim3(DM / 32, DM / 32, 3), dim3(32, 8)>>>(W, btP + OFF_W(0), DM, DM);
    conv_half<<<RC_BLOCKS, 256>>>(in_feats, xrP, NNODES * DM / 4);

    for (int l = 0; l < LL; l++) {
        // z = xr @ W  (+ fused el/er)
        gemm_z<<<dim3(1, MTILES), 256, G0SMEM>>>(
            xrP, btP + OFF_W(l), zP,
            attn_l + (size_t)l * DM, attn_r + (size_t)l * DM);

        if (l == 0) cudaStreamWaitEvent(0, evCsr, 0);
        gat_agg_ln<<<(NNODES + 7) / 8, 256>>>(conv_b + (size_t)l * DM, a_conv + l,
                                              ln_scale + (size_t)l * DM,
                                              ln_bias + (size_t)l * DM);

        if (l == 0) cudaStreamWaitEvent(0, evWt, 0);
        // out[l] = h + prelu(hn@W1+b1)@W2 + b2 ; xr = fp16(out[l])
        ff_fused<<<FTILES, 256, FF_SMEM>>>(
            hnP, btP + OFF_W1(l), btP + OFF_W2(l),
            b1 + (size_t)l * DFFH, a_ff + l, b2 + (size_t)l * DM,
            hP, out + (size_t)l * NNODES * DM, xrP);
    }
}